// round 1
// baseline (speedup 1.0000x reference)
#include <cuda_runtime.h>
#include <cuda_bf16.h>
#include <math.h>

#define N_NODES 50000
#define IN_CH   128
#define E_EDGES 400000
#define E_TOT   (E_EDGES + N_NODES)   // with self loops
#define HID     128                   // per-head channels of conv1
#define H1C     256                   // HEADS*HID
#define OUTC    64

// ---------------- scratch (device globals: allocation-free) ----------------
__device__ float g_H1  [(size_t)N_NODES * H1C];   // x @ W1
__device__ float g_ACC1[(size_t)N_NODES * H1C];   // layer-1 aggregation -> becomes H2 after ELU
__device__ float g_Gcat[(size_t)N_NODES * 128];   // [h2 @ W_mu | h2 @ W_ls]
__device__ float g_A1src[N_NODES * 2];
__device__ float g_A1dst[N_NODES * 2];
__device__ float g_A2src[N_NODES * 2];
__device__ float g_A2dst[N_NODES * 2];
__device__ float g_M1[N_NODES * 2];
__device__ float g_D1[N_NODES * 2];
__device__ float g_M2[N_NODES * 2];
__device__ float g_D2[N_NODES * 2];
__device__ float g_E1[(size_t)E_TOT * 2];
__device__ float g_E2[(size_t)E_TOT * 2];
__device__ float g_Wcat[256 * 128];
__device__ float g_attcat[256];        // [att_src_mu(64) att_src_ls(64) att_dst_mu(64) att_dst_ls(64)]

// ---------------- helpers ----------------
__device__ __forceinline__ void atomicMaxF(float* addr, float v) {
    if (v >= 0.f) atomicMax((int*)addr, __float_as_int(v));
    else          atomicMin((unsigned int*)addr, __float_as_uint(v));
}

__device__ __forceinline__ void red_add_v4(float* addr, float a, float b, float c, float d) {
    asm volatile("red.global.add.v4.f32 [%0], {%1,%2,%3,%4};"
                 :: "l"(addr), "f"(a), "f"(b), "f"(c), "f"(d) : "memory");
}

// ---------------- SGEMM: C[M,N] = A[M,K] @ B[K,N] ----------------
// BM=BN=64, BK=16, 256 threads, 4x4 micro-tile. N%64==0, K%16==0 assumed.
__global__ void sgemm64(const float* __restrict__ A, const float* __restrict__ B,
                        float* __restrict__ C, int M, int N, int K) {
    __shared__ float As[16][64];
    __shared__ float Bs[16][64];
    const int block_row = blockIdx.y * 64;
    const int block_col = blockIdx.x * 64;
    const int tid = threadIdx.x;
    const int tr = tid >> 4;       // 0..15
    const int tc = tid & 15;       // 0..15
    float acc[4][4] = {};

    const int arow = tid >> 2, ac = (tid & 3) * 4;
    const int brow = tid >> 4, bc = (tid & 15) * 4;
    const int agr = block_row + arow;

    for (int kt = 0; kt < K; kt += 16) {
        float4 av = make_float4(0.f, 0.f, 0.f, 0.f);
        if (agr < M) av = *(const float4*)&A[(size_t)agr * K + kt + ac];
        As[ac + 0][arow] = av.x; As[ac + 1][arow] = av.y;
        As[ac + 2][arow] = av.z; As[ac + 3][arow] = av.w;
        *(float4*)&Bs[brow][bc] = *(const float4*)&B[(size_t)(kt + brow) * N + block_col + bc];
        __syncthreads();
#pragma unroll
        for (int k = 0; k < 16; k++) {
            float a[4], b[4];
#pragma unroll
            for (int i = 0; i < 4; i++) a[i] = As[k][tr * 4 + i];
#pragma unroll
            for (int j = 0; j < 4; j++) b[j] = Bs[k][tc * 4 + j];
#pragma unroll
            for (int i = 0; i < 4; i++)
#pragma unroll
                for (int j = 0; j < 4; j++) acc[i][j] += a[i] * b[j];
        }
        __syncthreads();
    }
#pragma unroll
    for (int i = 0; i < 4; i++) {
        int gr = block_row + tr * 4 + i;
        if (gr < M)
            *(float4*)&C[(size_t)gr * N + block_col + tc * 4] =
                make_float4(acc[i][0], acc[i][1], acc[i][2], acc[i][3]);
    }
}

// ---------------- attention logits: one warp per (node, head) ----------------
__global__ void attn_logits_k(const float* __restrict__ G, const float* __restrict__ attsrc,
                              const float* __restrict__ attdst,
                              float* __restrict__ asrc, float* __restrict__ adst,
                              int C, int HC) {
    int w = (blockIdx.x * blockDim.x + threadIdx.x) >> 5;
    int lane = threadIdx.x & 31;
    if (w >= N_NODES * 2) return;
    int n = w >> 1, h = w & 1;
    const float* g = G + (size_t)n * HC + h * C;
    float ss = 0.f, sd = 0.f;
    for (int c = lane; c < C; c += 32) {
        float gv = g[c];
        ss += gv * attsrc[h * C + c];
        sd += gv * attdst[h * C + c];
    }
#pragma unroll
    for (int o = 16; o; o >>= 1) {
        ss += __shfl_xor_sync(0xffffffffu, ss, o);
        sd += __shfl_xor_sync(0xffffffffu, sd, o);
    }
    if (lane == 0) { asrc[n * 2 + h] = ss; adst[n * 2 + h] = sd; }
}

// ---------------- edge passes ----------------
__device__ __forceinline__ void edge_sd(int e, const int* __restrict__ ei, int& s, int& d) {
    if (e < E_EDGES) { s = ei[e]; d = ei[E_EDGES + e]; }
    else             { s = d = e - E_EDGES; }
}

__global__ void edge_max_k(const float* __restrict__ asrc, const float* __restrict__ adst,
                           const int* __restrict__ ei, float* __restrict__ mmax) {
    int i = blockIdx.x * blockDim.x + threadIdx.x;
    if (i >= E_TOT * 2) return;
    int e = i >> 1, h = i & 1, s, d;
    edge_sd(e, ei, s, d);
    float v = asrc[s * 2 + h] + adst[d * 2 + h];
    v = v > 0.f ? v : 0.2f * v;
    atomicMaxF(&mmax[d * 2 + h], v);
}

__global__ void edge_exp_k(const float* __restrict__ asrc, const float* __restrict__ adst,
                           const int* __restrict__ ei, const float* __restrict__ mmax,
                           float* __restrict__ eexp, float* __restrict__ denom) {
    int i = blockIdx.x * blockDim.x + threadIdx.x;
    if (i >= E_TOT * 2) return;
    int e = i >> 1, h = i & 1, s, d;
    edge_sd(e, ei, s, d);
    float v = asrc[s * 2 + h] + adst[d * 2 + h];
    v = v > 0.f ? v : 0.2f * v;
    float ex = __expf(v - mmax[d * 2 + h]);
    eexp[(size_t)e * 2 + h] = ex;
    atomicAdd(&denom[d * 2 + h], ex);
}

// ---------------- layer-1 scatter: 64 threads per edge (2 heads x 128 ch) ----------------
__global__ void scatter1_k(const float* __restrict__ Hsrc, const float* __restrict__ eexp,
                           const float* __restrict__ denom, const int* __restrict__ ei,
                           float* __restrict__ acc) {
    int idx = blockIdx.x * blockDim.x + threadIdx.x;
    int e = idx >> 6;
    if (e >= E_TOT) return;
    int lane = idx & 63;
    int h = lane >> 5;
    int c4 = (lane & 31) * 4;
    int s, d;
    edge_sd(e, ei, s, d);
    float alpha = eexp[(size_t)e * 2 + h] / (denom[d * 2 + h] + 1e-16f);
    float4 v = *(const float4*)&Hsrc[(size_t)s * H1C + h * HID + c4];
    red_add_v4(&acc[(size_t)d * H1C + h * HID + c4],
               v.x * alpha, v.y * alpha, v.z * alpha, v.w * alpha);
}

// ---------------- ELU + bias (in place): acc -> h2 ----------------
__global__ void elu_bias_k(float* __restrict__ acc, const float* __restrict__ b1) {
    size_t i = (size_t)blockIdx.x * blockDim.x + threadIdx.x;
    if (i >= (size_t)N_NODES * H1C) return;
    float v = acc[i] + b1[i & (H1C - 1)];
    acc[i] = v > 0.f ? v : expm1f(v);
}

// ---------------- concat W_mu|W_ls and att vectors ----------------
__global__ void concat_k(const float* __restrict__ Wmu, const float* __restrict__ Wls,
                         const float* __restrict__ asmu, const float* __restrict__ asls,
                         const float* __restrict__ admu, const float* __restrict__ adls,
                         float* __restrict__ Wcat, float* __restrict__ attcat) {
    int i = blockIdx.x * blockDim.x + threadIdx.x;
    if (i < 256 * 128) {
        int k = i >> 7, c = i & 127;
        Wcat[i] = (c < 64) ? Wmu[k * 64 + c] : Wls[k * 64 + (c - 64)];
    } else if (i < 256 * 128 + 256) {
        int j = i - 256 * 128;
        float v;
        if      (j < 64)  v = asmu[j];
        else if (j < 128) v = asls[j - 64];
        else if (j < 192) v = admu[j - 128];
        else              v = adls[j - 192];
        attcat[j] = v;
    }
}

// ---------------- fill kernel (for -inf-ish max init) ----------------
__global__ void fill_k(float* __restrict__ p, float v, int n) {
    int i = blockIdx.x * blockDim.x + threadIdx.x;
    if (i < n) p[i] = v;
}

// ---------------- layer-2 scatter: 32 threads per edge (mu:64 + ls:64) ----------------
__global__ void scatter2_k(const float* __restrict__ Gcat, const float* __restrict__ eexp,
                           const float* __restrict__ denom, const int* __restrict__ ei,
                           float* __restrict__ out) {
    int idx = blockIdx.x * blockDim.x + threadIdx.x;
    int e = idx >> 5;
    if (e >= E_TOT) return;
    int lane = idx & 31;
    int h = lane >> 4;             // 0 = mu, 1 = logstd
    int c4 = (lane & 15) * 4;
    int s, d;
    edge_sd(e, ei, s, d);
    float alpha = eexp[(size_t)e * 2 + h] / (denom[d * 2 + h] + 1e-16f);
    float4 v = *(const float4*)&Gcat[(size_t)s * 128 + h * 64 + c4];
    float* dp = out + (size_t)h * N_NODES * OUTC + (size_t)d * OUTC + c4;
    red_add_v4(dp, v.x * alpha, v.y * alpha, v.z * alpha, v.w * alpha);
}

// ---------------- final bias add ----------------
__global__ void bias2_k(float* __restrict__ out, const float* __restrict__ bmu,
                        const float* __restrict__ bls) {
    size_t i = (size_t)blockIdx.x * blockDim.x + threadIdx.x;
    if (i >= (size_t)N_NODES * OUTC) return;
    int c = i & (OUTC - 1);
    out[i] += bmu[c];
    out[(size_t)N_NODES * OUTC + i] += bls[c];
}

// ---------------- launch ----------------
extern "C" void kernel_launch(void* const* d_in, const int* in_sizes, int n_in,
                              void* d_out, int out_size) {
    const float* x        = (const float*)d_in[0];
    const int*   ei       = (const int*)  d_in[1];
    const float* W1       = (const float*)d_in[2];
    const float* att_src1 = (const float*)d_in[3];
    const float* att_dst1 = (const float*)d_in[4];
    const float* b1       = (const float*)d_in[5];
    const float* W_mu     = (const float*)d_in[6];
    const float* as_mu    = (const float*)d_in[7];
    const float* ad_mu    = (const float*)d_in[8];
    const float* b_mu     = (const float*)d_in[9];
    const float* W_ls     = (const float*)d_in[10];
    const float* as_ls    = (const float*)d_in[11];
    const float* ad_ls    = (const float*)d_in[12];
    const float* b_ls     = (const float*)d_in[13];
    float* out = (float*)d_out;

    float *H1, *ACC1, *Gcat, *A1s, *A1d, *A2s, *A2d, *M1, *D1, *M2, *D2, *E1, *E2, *Wcat, *attcat;
    cudaGetSymbolAddress((void**)&H1,   g_H1);
    cudaGetSymbolAddress((void**)&ACC1, g_ACC1);
    cudaGetSymbolAddress((void**)&Gcat, g_Gcat);
    cudaGetSymbolAddress((void**)&A1s,  g_A1src);
    cudaGetSymbolAddress((void**)&A1d,  g_A1dst);
    cudaGetSymbolAddress((void**)&A2s,  g_A2src);
    cudaGetSymbolAddress((void**)&A2d,  g_A2dst);
    cudaGetSymbolAddress((void**)&M1,   g_M1);
    cudaGetSymbolAddress((void**)&D1,   g_D1);
    cudaGetSymbolAddress((void**)&M2,   g_M2);
    cudaGetSymbolAddress((void**)&D2,   g_D2);
    cudaGetSymbolAddress((void**)&E1,   g_E1);
    cudaGetSymbolAddress((void**)&E2,   g_E2);
    cudaGetSymbolAddress((void**)&Wcat, g_Wcat);
    cudaGetSymbolAddress((void**)&attcat, g_attcat);

    // ---- init ----
    cudaMemsetAsync(ACC1, 0, (size_t)N_NODES * H1C * sizeof(float));
    cudaMemsetAsync(D1,   0, N_NODES * 2 * sizeof(float));
    cudaMemsetAsync(D2,   0, N_NODES * 2 * sizeof(float));
    cudaMemsetAsync(out,  0, (size_t)out_size * sizeof(float));
    fill_k<<<(N_NODES * 2 + 255) / 256, 256>>>(M1, -1e30f, N_NODES * 2);
    fill_k<<<(N_NODES * 2 + 255) / 256, 256>>>(M2, -1e30f, N_NODES * 2);

    // ---- layer 1 ----
    {
        dim3 grid(H1C / 64, (N_NODES + 63) / 64);
        sgemm64<<<grid, 256>>>(x, W1, H1, N_NODES, H1C, IN_CH);
    }
    attn_logits_k<<<(N_NODES * 2 * 32 + 255) / 256, 256>>>(H1, att_src1, att_dst1, A1s, A1d, HID, H1C);
    edge_max_k<<<(E_TOT * 2 + 255) / 256, 256>>>(A1s, A1d, ei, M1);
    edge_exp_k<<<(E_TOT * 2 + 255) / 256, 256>>>(A1s, A1d, ei, M1, E1, D1);
    scatter1_k<<<((size_t)E_TOT * 64 + 255) / 256, 256>>>(H1, E1, D1, ei, ACC1);
    elu_bias_k<<<((size_t)N_NODES * H1C + 255) / 256, 256>>>(ACC1, b1);

    // ---- weights / att concat (independent of layer 1; cheap) ----
    concat_k<<<(256 * 128 + 256 + 255) / 256, 256>>>(W_mu, W_ls, as_mu, as_ls, ad_mu, ad_ls, Wcat, attcat);

    // ---- layer 2 (mu & logstd fused as 2 pseudo-heads) ----
    {
        dim3 grid(128 / 64, (N_NODES + 63) / 64);
        sgemm64<<<grid, 256>>>(ACC1, Wcat, Gcat, N_NODES, 128, H1C);
    }
    attn_logits_k<<<(N_NODES * 2 * 32 + 255) / 256, 256>>>(Gcat, attcat, attcat + 128, A2s, A2d, OUTC, 128);
    edge_max_k<<<(E_TOT * 2 + 255) / 256, 256>>>(A2s, A2d, ei, M2);
    edge_exp_k<<<(E_TOT * 2 + 255) / 256, 256>>>(A2s, A2d, ei, M2, E2, D2);
    scatter2_k<<<((size_t)E_TOT * 32 + 255) / 256, 256>>>(Gcat, E2, D2, ei, out);
    bias2_k<<<((size_t)N_NODES * OUTC + 255) / 256, 256>>>(out, b_mu, b_ls);
}

// round 3
// speedup vs baseline: 1.2429x; 1.2429x over previous
#include <cuda_runtime.h>
#include <cuda_bf16.h>
#include <math.h>
#include <stdint.h>

#define N_NODES 50000
#define IN_CH   128
#define E_EDGES 400000
#define E_TOT   (E_EDGES + N_NODES)   // with self loops
#define HID     128                   // per-head channels of conv1
#define H1C     256                   // HEADS*HID
#define OUTC    64

// ---------------- scratch (device globals: allocation-free) ----------------
__device__ float g_H1  [(size_t)N_NODES * H1C];   // x @ W1 (fp32)
__device__ float g_ACC1[(size_t)N_NODES * H1C];   // layer-1 aggregation
__device__ float g_Gcat[(size_t)N_NODES * 128];   // [h2 @ W_mu | h2 @ W_ls]
__device__ __nv_bfloat16 g_Xhi[(size_t)N_NODES * IN_CH];
__device__ __nv_bfloat16 g_Xlo[(size_t)N_NODES * IN_CH];
__device__ __nv_bfloat16 g_H2hi[(size_t)N_NODES * H1C];
__device__ __nv_bfloat16 g_H2lo[(size_t)N_NODES * H1C];
__device__ __nv_bfloat16 g_W1T_hi[256 * 128];   // [N=256 rows][K=128]
__device__ __nv_bfloat16 g_W1T_lo[256 * 128];
__device__ __nv_bfloat16 g_WcT_hi[128 * 256];   // [N=128 rows][K=256]
__device__ __nv_bfloat16 g_WcT_lo[128 * 256];
__device__ float g_A1src[N_NODES * 2];
__device__ float g_A1dst[N_NODES * 2];
__device__ float g_A2src[N_NODES * 2];
__device__ float g_A2dst[N_NODES * 2];
__device__ float g_M1[N_NODES * 2];
__device__ float g_D1[N_NODES * 2];
__device__ float g_M2[N_NODES * 2];
__device__ float g_D2[N_NODES * 2];
__device__ float g_E1[(size_t)E_TOT * 2];
__device__ float g_E2[(size_t)E_TOT * 2];
__device__ float g_att2src[128];   // [as_mu(64) | as_ls(64)]
__device__ float g_att2dst[128];   // [ad_mu(64) | ad_ls(64)]

// ---------------- low-level helpers ----------------
__device__ __forceinline__ uint32_t smem_u32(const void* p) {
    uint32_t a;
    asm("{ .reg .u64 t; cvta.to.shared.u64 t, %1; cvt.u32.u64 %0, t; }" : "=r"(a) : "l"(p));
    return a;
}
__device__ __forceinline__ void ldsm4(uint32_t* r, uint32_t addr) {
    asm volatile("ldmatrix.sync.aligned.m8n8.x4.shared.b16 {%0,%1,%2,%3}, [%4];"
                 : "=r"(r[0]), "=r"(r[1]), "=r"(r[2]), "=r"(r[3]) : "r"(addr));
}
__device__ __forceinline__ void mma_bf16(float* c, const uint32_t* a, uint32_t b0, uint32_t b1) {
    asm volatile("mma.sync.aligned.m16n8k16.row.col.f32.bf16.bf16.f32 "
                 "{%0,%1,%2,%3}, {%4,%5,%6,%7}, {%8,%9}, {%0,%1,%2,%3};"
                 : "+f"(c[0]), "+f"(c[1]), "+f"(c[2]), "+f"(c[3])
                 : "r"(a[0]), "r"(a[1]), "r"(a[2]), "r"(a[3]), "r"(b0), "r"(b1));
}

// ============================================================================
// Tensor-core GEMM (mma.sync bf16, hi/lo 3-product split) + fused attn logits.
// C[M, NTOT] = A[M, K] @ B^T, B stored [NTOT][K] K-major.
// CTA tile 128x128, 8 warps of 32x64. Grid: (ceil(M/128), NTOT/128).
// Epilogue computes per-row logits: sum_c C[r, c] * attsrc[c] (and attdst),
// written per head of CHEAD columns (CHEAD = 128 -> head = blockIdx.y;
// CHEAD = 64 -> head = warp-column).
// ============================================================================
template<int K, int NTOT, int CHEAD>
__global__ __launch_bounds__(256, 2) void gemm_mma(
    const __nv_bfloat16* __restrict__ Ahi, const __nv_bfloat16* __restrict__ Alo,
    const __nv_bfloat16* __restrict__ Bhi, const __nv_bfloat16* __restrict__ Blo,
    float* __restrict__ C,
    const float* __restrict__ attsrc, const float* __restrict__ attdst,
    float* __restrict__ asrc, float* __restrict__ adst, int M)
{
    __shared__ __align__(16) __nv_bfloat16 sAh[128 * 32];
    __shared__ __align__(16) __nv_bfloat16 sAl[128 * 32];
    __shared__ __align__(16) __nv_bfloat16 sBh[128 * 32];
    __shared__ __align__(16) __nv_bfloat16 sBl[128 * 32];
    __shared__ float sAtt[2][128];
    __shared__ float sRed[2][128][2];   // [warp-col][row][src/dst]

    const int tid = threadIdx.x;
    const int lane = tid & 31;
    const int wid = tid >> 5;
    const int wr = wid & 3;        // warp row group (32 rows each)
    const int wc = wid >> 2;       // warp col group (64 cols each)
    const int m0 = blockIdx.x * 128;
    const int n0 = blockIdx.y * 128;

    for (int i = tid; i < 128; i += 256) {
        sAtt[0][i] = attsrc[n0 + i];
        sAtt[1][i] = attdst[n0 + i];
    }

    const uint32_t sAhB = smem_u32(sAh), sAlB = smem_u32(sAl);
    const uint32_t sBhB = smem_u32(sBh), sBlB = smem_u32(sBl);

    float acc[2][8][4];
#pragma unroll
    for (int i = 0; i < 2; i++)
#pragma unroll
        for (int j = 0; j < 8; j++)
#pragma unroll
            for (int l = 0; l < 4; l++) acc[i][j][l] = 0.f;

    // ldmatrix lane-address components (constant across k-steps)
    const int a_row = wr * 32 + (lane & 7) + ((lane >> 3) & 1) * 8;   // + mt*16
    const int a_chA = lane >> 4;                                      // + k16*2
    const int b_row = wc * 64 + (lane & 7) + (lane >> 4) * 8;         // + ntg*16
    const int b_chB = (lane >> 3) & 1;                                // + k16*2

    for (int ks = 0; ks < K / 32; ks++) {
        // ---- global -> shared (XOR-swizzled 16B chunks) ----
#pragma unroll
        for (int j = 0; j < 2; j++) {
            int idx = tid + j * 256;
            int row = idx >> 2, ch = idx & 3;
            uint32_t soff = row * 64 + ((ch ^ (row & 3)) << 4);
            int grA = m0 + row;
            size_t gofs = (size_t)grA * K + ks * 32 + ch * 8;
            uint4 va = make_uint4(0u, 0u, 0u, 0u), vb = va;
            if (grA < M) { va = *(const uint4*)(Ahi + gofs); vb = *(const uint4*)(Alo + gofs); }
            *(uint4*)((char*)sAh + soff) = va;
            *(uint4*)((char*)sAl + soff) = vb;
            size_t gofsB = (size_t)(n0 + row) * K + ks * 32 + ch * 8;
            *(uint4*)((char*)sBh + soff) = *(const uint4*)(Bhi + gofsB);
            *(uint4*)((char*)sBl + soff) = *(const uint4*)(Blo + gofsB);
        }
        __syncthreads();

#pragma unroll
        for (int k16 = 0; k16 < 2; k16++) {
            uint32_t ah[2][4], al[2][4];
#pragma unroll
            for (int mt = 0; mt < 2; mt++) {
                int row = a_row + mt * 16;
                int ch = k16 * 2 + a_chA;
                uint32_t off = row * 64 + ((ch ^ (row & 3)) << 4);
                ldsm4(ah[mt], sAhB + off);
                ldsm4(al[mt], sAlB + off);
            }
#pragma unroll
            for (int ntg = 0; ntg < 4; ntg++) {
                int row = b_row + ntg * 16;
                int ch = k16 * 2 + b_chB;
                uint32_t off = row * 64 + ((ch ^ (row & 3)) << 4);
                uint32_t bh[4], bl[4];
                ldsm4(bh, sBhB + off);
                ldsm4(bl, sBlB + off);
#pragma unroll
                for (int mt = 0; mt < 2; mt++) {
                    mma_bf16(acc[mt][ntg * 2 + 0], ah[mt], bh[0], bh[1]);
                    mma_bf16(acc[mt][ntg * 2 + 0], al[mt], bh[0], bh[1]);
                    mma_bf16(acc[mt][ntg * 2 + 0], ah[mt], bl[0], bl[1]);
                    mma_bf16(acc[mt][ntg * 2 + 1], ah[mt], bh[2], bh[3]);
                    mma_bf16(acc[mt][ntg * 2 + 1], al[mt], bh[2], bh[3]);
                    mma_bf16(acc[mt][ntg * 2 + 1], ah[mt], bl[2], bl[3]);
                }
            }
        }
        __syncthreads();
    }

    // ---- epilogue: store C + fused logits ----
    float pss[2][2] = {}, psd[2][2] = {};
#pragma unroll
    for (int mt = 0; mt < 2; mt++) {
        int rloc = wr * 32 + mt * 16 + (lane >> 2);
        int grow0 = m0 + rloc, grow1 = grow0 + 8;
#pragma unroll
        for (int nt = 0; nt < 8; nt++) {
            int cl = wc * 64 + nt * 8 + (lane & 3) * 2;   // local col in tile
            float a0s = sAtt[0][cl], a1s = sAtt[0][cl + 1];
            float a0d = sAtt[1][cl], a1d = sAtt[1][cl + 1];
            float c0 = acc[mt][nt][0], c1 = acc[mt][nt][1];
            float c2 = acc[mt][nt][2], c3 = acc[mt][nt][3];
            pss[mt][0] += c0 * a0s + c1 * a1s;  psd[mt][0] += c0 * a0d + c1 * a1d;
            pss[mt][1] += c2 * a0s + c3 * a1s;  psd[mt][1] += c2 * a0d + c3 * a1d;
            if (grow0 < M) *(float2*)&C[(size_t)grow0 * NTOT + n0 + cl] = make_float2(c0, c1);
            if (grow1 < M) *(float2*)&C[(size_t)grow1 * NTOT + n0 + cl] = make_float2(c2, c3);
        }
    }
#pragma unroll
    for (int mt = 0; mt < 2; mt++)
#pragma unroll
        for (int h8 = 0; h8 < 2; h8++) {
            float vs = pss[mt][h8], vd = psd[mt][h8];
            vs += __shfl_xor_sync(0xffffffffu, vs, 1); vs += __shfl_xor_sync(0xffffffffu, vs, 2);
            vd += __shfl_xor_sync(0xffffffffu, vd, 1); vd += __shfl_xor_sync(0xffffffffu, vd, 2);
            if ((lane & 3) == 0) {
                int r = wr * 32 + mt * 16 + h8 * 8 + (lane >> 2);
                sRed[wc][r][0] = vs;
                sRed[wc][r][1] = vd;
            }
        }
    __syncthreads();
    for (int r = tid; r < 128; r += 256) {
        int node = m0 + r;
        if (node >= M) continue;
        if (CHEAD == 128) {
            int h = n0 >> 7;
            asrc[node * 2 + h] = sRed[0][r][0] + sRed[1][r][0];
            adst[node * 2 + h] = sRed[0][r][1] + sRed[1][r][1];
        } else {
            asrc[node * 2 + 0] = sRed[0][r][0];  adst[node * 2 + 0] = sRed[0][r][1];
            asrc[node * 2 + 1] = sRed[1][r][0];  adst[node * 2 + 1] = sRed[1][r][1];
        }
    }
}

// ---------------- hi/lo split helpers ----------------
__device__ __forceinline__ void split2(float v, __nv_bfloat16& h, __nv_bfloat16& l) {
    h = __float2bfloat16(v);
    l = __float2bfloat16(v - __bfloat162float(h));
}

__global__ void split_x_k(const float* __restrict__ x,
                          __nv_bfloat16* __restrict__ xh, __nv_bfloat16* __restrict__ xl) {
    size_t i = (size_t)blockIdx.x * blockDim.x + threadIdx.x;
    if (i >= (size_t)N_NODES * IN_CH) return;
    split2(x[i], xh[i], xl[i]);
}

// build transposed hi/lo weights + concat att vectors for layer 2
__global__ void prep_k(const float* __restrict__ W1,
                       const float* __restrict__ Wmu, const float* __restrict__ Wls,
                       const float* __restrict__ asmu, const float* __restrict__ asls,
                       const float* __restrict__ admu, const float* __restrict__ adls,
                       __nv_bfloat16* __restrict__ W1Th, __nv_bfloat16* __restrict__ W1Tl,
                       __nv_bfloat16* __restrict__ WcTh, __nv_bfloat16* __restrict__ WcTl,
                       float* __restrict__ a2s, float* __restrict__ a2d) {
    int i = blockIdx.x * blockDim.x + threadIdx.x;
    if (i < 256 * 128) {                       // W1T [n=256][k=128]
        int n = i >> 7, k = i & 127;
        split2(W1[k * 256 + n], W1Th[i], W1Tl[i]);
    } else if (i < 2 * 256 * 128) {            // WcatT [n=128][k=256]
        int j = i - 256 * 128;
        int n = j >> 8, k = j & 255;
        float w = (n < 64) ? Wmu[k * 64 + n] : Wls[k * 64 + (n - 64)];
        split2(w, WcTh[j], WcTl[j]);
    } else if (i < 2 * 256 * 128 + 128) {
        int j = i - 2 * 256 * 128;
        a2s[j] = (j < 64) ? asmu[j] : asls[j - 64];
    } else if (i < 2 * 256 * 128 + 256) {
        int j = i - 2 * 256 * 128 - 128;
        a2d[j] = (j < 64) ? admu[j] : adls[j - 64];
    }
}

// ---------------- helpers ----------------
__device__ __forceinline__ void atomicMaxF(float* addr, float v) {
    if (v >= 0.f) atomicMax((int*)addr, __float_as_int(v));
    else          atomicMin((unsigned int*)addr, __float_as_uint(v));
}
__device__ __forceinline__ void red_add_v4(float* addr, float a, float b, float c, float d) {
    asm volatile("red.global.add.v4.f32 [%0], {%1,%2,%3,%4};"
                 :: "l"(addr), "f"(a), "f"(b), "f"(c), "f"(d) : "memory");
}

// ---------------- edge passes ----------------
__device__ __forceinline__ void edge_sd(int e, const int* __restrict__ ei, int& s, int& d) {
    if (e < E_EDGES) { s = ei[e]; d = ei[E_EDGES + e]; }
    else             { s = d = e - E_EDGES; }
}

__global__ void edge_max_k(const float* __restrict__ asrc, const float* __restrict__ adst,
                           const int* __restrict__ ei, float* __restrict__ mmax) {
    int i = blockIdx.x * blockDim.x + threadIdx.x;
    if (i >= E_TOT * 2) return;
    int e = i >> 1, h = i & 1, s, d;
    edge_sd(e, ei, s, d);
    float v = asrc[s * 2 + h] + adst[d * 2 + h];
    v = v > 0.f ? v : 0.2f * v;
    atomicMaxF(&mmax[d * 2 + h], v);
}

__global__ void edge_exp_k(const float* __restrict__ asrc, const float* __restrict__ adst,
                           const int* __restrict__ ei, const float* __restrict__ mmax,
                           float* __restrict__ eexp, float* __restrict__ denom) {
    int i = blockIdx.x * blockDim.x + threadIdx.x;
    if (i >= E_TOT * 2) return;
    int e = i >> 1, h = i & 1, s, d;
    edge_sd(e, ei, s, d);
    float v = asrc[s * 2 + h] + adst[d * 2 + h];
    v = v > 0.f ? v : 0.2f * v;
    float ex = __expf(v - mmax[d * 2 + h]);
    eexp[(size_t)e * 2 + h] = ex;
    atomicAdd(&denom[d * 2 + h], ex);
}

// ---------------- layer-1 scatter: 64 threads per edge ----------------
__global__ void scatter1_k(const float* __restrict__ Hsrc, const float* __restrict__ eexp,
                           const float* __restrict__ denom, const int* __restrict__ ei,
                           float* __restrict__ acc) {
    int idx = blockIdx.x * blockDim.x + threadIdx.x;
    int e = idx >> 6;
    if (e >= E_TOT) return;
    int lane = idx & 63;
    int h = lane >> 5;
    int c4 = (lane & 31) * 4;
    int s, d;
    edge_sd(e, ei, s, d);
    float alpha = eexp[(size_t)e * 2 + h] / (denom[d * 2 + h] + 1e-16f);
    float4 v = *(const float4*)&Hsrc[(size_t)s * H1C + h * HID + c4];
    red_add_v4(&acc[(size_t)d * H1C + h * HID + c4],
               v.x * alpha, v.y * alpha, v.z * alpha, v.w * alpha);
}

// ---------------- ELU + bias, then hi/lo split to bf16 ----------------
__global__ void elu_bias_split_k(const float* __restrict__ acc, const float* __restrict__ b1,
                                 __nv_bfloat16* __restrict__ h2h, __nv_bfloat16* __restrict__ h2l) {
    size_t i = (size_t)blockIdx.x * blockDim.x + threadIdx.x;
    if (i >= (size_t)N_NODES * H1C) return;
    float v = acc[i] + b1[i & (H1C - 1)];
    v = v > 0.f ? v : expm1f(v);
    split2(v, h2h[i], h2l[i]);
}

__global__ void fill_k(float* __restrict__ p, float v, int n) {
    int i = blockIdx.x * blockDim.x + threadIdx.x;
    if (i < n) p[i] = v;
}

// ---------------- layer-2 scatter: 32 threads per edge ----------------
__global__ void scatter2_k(const float* __restrict__ Gcat, const float* __restrict__ eexp,
                           const float* __restrict__ denom, const int* __restrict__ ei,
                           float* __restrict__ out) {
    int idx = blockIdx.x * blockDim.x + threadIdx.x;
    int e = idx >> 5;
    if (e >= E_TOT) return;
    int lane = idx & 31;
    int h = lane >> 4;             // 0 = mu, 1 = logstd
    int c4 = (lane & 15) * 4;
    int s, d;
    edge_sd(e, ei, s, d);
    float alpha = eexp[(size_t)e * 2 + h] / (denom[d * 2 + h] + 1e-16f);
    float4 v = *(const float4*)&Gcat[(size_t)s * 128 + h * 64 + c4];
    float* dp = out + (size_t)h * N_NODES * OUTC + (size_t)d * OUTC + c4;
    red_add_v4(dp, v.x * alpha, v.y * alpha, v.z * alpha, v.w * alpha);
}

__global__ void bias2_k(float* __restrict__ out, const float* __restrict__ bmu,
                        const float* __restrict__ bls) {
    size_t i = (size_t)blockIdx.x * blockDim.x + threadIdx.x;
    if (i >= (size_t)N_NODES * OUTC) return;
    int c = i & (OUTC - 1);
    out[i] += bmu[c];
    out[(size_t)N_NODES * OUTC + i] += bls[c];
}

// ---------------- launch ----------------
extern "C" void kernel_launch(void* const* d_in, const int* in_sizes, int n_in,
                              void* d_out, int out_size) {
    const float* x        = (const float*)d_in[0];
    const int*   ei       = (const int*)  d_in[1];
    const float* W1       = (const float*)d_in[2];
    const float* att_src1 = (const float*)d_in[3];
    const float* att_dst1 = (const float*)d_in[4];
    const float* b1       = (const float*)d_in[5];
    const float* W_mu     = (const float*)d_in[6];
    const float* as_mu    = (const float*)d_in[7];
    const float* ad_mu    = (const float*)d_in[8];
    const float* b_mu     = (const float*)d_in[9];
    const float* W_ls     = (const float*)d_in[10];
    const float* as_ls    = (const float*)d_in[11];
    const float* ad_ls    = (const float*)d_in[12];
    const float* b_ls     = (const float*)d_in[13];
    float* out = (float*)d_out;

    float *H1, *ACC1, *Gcat, *A1s, *A1d, *A2s, *A2d, *M1, *D1, *M2, *D2, *E1, *E2, *a2s, *a2d;
    __nv_bfloat16 *Xhi, *Xlo, *H2hi, *H2lo, *W1Th, *W1Tl, *WcTh, *WcTl;
    cudaGetSymbolAddress((void**)&H1,   g_H1);
    cudaGetSymbolAddress((void**)&ACC1, g_ACC1);
    cudaGetSymbolAddress((void**)&Gcat, g_Gcat);
    cudaGetSymbolAddress((void**)&A1s,  g_A1src);
    cudaGetSymbolAddress((void**)&A1d,  g_A1dst);
    cudaGetSymbolAddress((void**)&A2s,  g_A2src);
    cudaGetSymbolAddress((void**)&A2d,  g_A2dst);
    cudaGetSymbolAddress((void**)&M1,   g_M1);
    cudaGetSymbolAddress((void**)&D1,   g_D1);
    cudaGetSymbolAddress((void**)&M2,   g_M2);
    cudaGetSymbolAddress((void**)&D2,   g_D2);
    cudaGetSymbolAddress((void**)&E1,   g_E1);
    cudaGetSymbolAddress((void**)&E2,   g_E2);
    cudaGetSymbolAddress((void**)&a2s,  g_att2src);
    cudaGetSymbolAddress((void**)&a2d,  g_att2dst);
    cudaGetSymbolAddress((void**)&Xhi,  g_Xhi);
    cudaGetSymbolAddress((void**)&Xlo,  g_Xlo);
    cudaGetSymbolAddress((void**)&H2hi, g_H2hi);
    cudaGetSymbolAddress((void**)&H2lo, g_H2lo);
    cudaGetSymbolAddress((void**)&W1Th, g_W1T_hi);
    cudaGetSymbolAddress((void**)&W1Tl, g_W1T_lo);
    cudaGetSymbolAddress((void**)&WcTh, g_WcT_hi);
    cudaGetSymbolAddress((void**)&WcTl, g_WcT_lo);

    // ---- init ----
    cudaMemsetAsync(ACC1, 0, (size_t)N_NODES * H1C * sizeof(float));
    cudaMemsetAsync(D1,   0, N_NODES * 2 * sizeof(float));
    cudaMemsetAsync(D2,   0, N_NODES * 2 * sizeof(float));
    cudaMemsetAsync(out,  0, (size_t)out_size * sizeof(float));
    fill_k<<<(N_NODES * 2 + 255) / 256, 256>>>(M1, -1e30f, N_NODES * 2);
    fill_k<<<(N_NODES * 2 + 255) / 256, 256>>>(M2, -1e30f, N_NODES * 2);

    // ---- data prep ----
    split_x_k<<<((size_t)N_NODES * IN_CH + 255) / 256, 256>>>(x, Xhi, Xlo);
    prep_k<<<(2 * 256 * 128 + 256 + 255) / 256, 256>>>(W1, W_mu, W_ls, as_mu, as_ls, ad_mu, ad_ls,
                                                       W1Th, W1Tl, WcTh, WcTl, a2s, a2d);

    const int gx = (N_NODES + 127) / 128;

    // ---- layer 1: bf16 mma GEMM + fused attention logits ----
    gemm_mma<128, 256, 128><<<dim3(gx, 2), 256>>>(
        Xhi, Xlo, W1Th, W1Tl, H1, att_src1, att_dst1, A1s, A1d, N_NODES);
    edge_max_k<<<(E_TOT * 2 + 255) / 256, 256>>>(A1s, A1d, ei, M1);
    edge_exp_k<<<(E_TOT * 2 + 255) / 256, 256>>>(A1s, A1d, ei, M1, E1, D1);
    scatter1_k<<<((size_t)E_TOT * 64 + 255) / 256, 256>>>(H1, E1, D1, ei, ACC1);
    elu_bias_split_k<<<((size_t)N_NODES * H1C + 255) / 256, 256>>>(ACC1, b1, H2hi, H2lo);

    // ---- layer 2: bf16 mma GEMM (mu & logstd fused) + fused logits ----
    gemm_mma<256, 128, 64><<<dim3(gx, 1), 256>>>(
        H2hi, H2lo, WcTh, WcTl, Gcat, a2s, a2d, A2s, A2d, N_NODES);
    edge_max_k<<<(E_TOT * 2 + 255) / 256, 256>>>(A2s, A2d, ei, M2);
    edge_exp_k<<<(E_TOT * 2 + 255) / 256, 256>>>(A2s, A2d, ei, M2, E2, D2);
    scatter2_k<<<((size_t)E_TOT * 32 + 255) / 256, 256>>>(Gcat, E2, D2, ei, out);
    bias2_k<<<((size_t)N_NODES * OUTC + 255) / 256, 256>>>(out, b_mu, b_ls);
}

// round 4
// speedup vs baseline: 2.2537x; 1.8133x over previous
#include <cuda_runtime.h>
#include <cuda_bf16.h>
#include <math.h>
#include <stdint.h>

#define N_NODES 50000
#define IN_CH   128
#define E_EDGES 400000
#define E_TOT   (E_EDGES + N_NODES)   // with self loops
#define HID     128                   // per-head channels of conv1
#define H1C     256                   // HEADS*HID
#define OUTC    64
#define NBLK    ((N_NODES + 255) / 256)   // scan blocks

// ---------------- scratch (device globals: allocation-free) ----------------
__device__ float g_H1  [(size_t)N_NODES * H1C];   // x @ W1 (fp32)
__device__ float g_Gcat[(size_t)N_NODES * 128];   // [h2 @ W_mu | h2 @ W_ls]
__device__ __nv_bfloat16 g_Xhi[(size_t)N_NODES * IN_CH];
__device__ __nv_bfloat16 g_Xlo[(size_t)N_NODES * IN_CH];
__device__ __nv_bfloat16 g_H2hi[(size_t)N_NODES * H1C];
__device__ __nv_bfloat16 g_H2lo[(size_t)N_NODES * H1C];
__device__ __nv_bfloat16 g_W1T_hi[256 * 128];   // [N=256 rows][K=128]
__device__ __nv_bfloat16 g_W1T_lo[256 * 128];
__device__ __nv_bfloat16 g_WcT_hi[128 * 256];   // [N=128 rows][K=256]
__device__ __nv_bfloat16 g_WcT_lo[128 * 256];
__device__ float g_A1src[N_NODES * 2];
__device__ float g_A1dst[N_NODES * 2];
__device__ float g_A2src[N_NODES * 2];
__device__ float g_A2dst[N_NODES * 2];
__device__ float g_att2src[128];   // [as_mu(64) | as_ls(64)]
__device__ float g_att2dst[128];   // [ad_mu(64) | ad_ls(64)]
// CSR
__device__ int g_deg[N_NODES];
__device__ int g_ptr[N_NODES + 1];
__device__ int g_cursor[N_NODES];
__device__ int g_csrsrc[E_TOT];
__device__ int g_blockSum[NBLK];
__device__ int g_blockOff[NBLK];

// ---------------- low-level helpers ----------------
__device__ __forceinline__ uint32_t smem_u32(const void* p) {
    uint32_t a;
    asm("{ .reg .u64 t; cvta.to.shared.u64 t, %1; cvt.u32.u64 %0, t; }" : "=r"(a) : "l"(p));
    return a;
}
__device__ __forceinline__ void ldsm4(uint32_t* r, uint32_t addr) {
    asm volatile("ldmatrix.sync.aligned.m8n8.x4.shared.b16 {%0,%1,%2,%3}, [%4];"
                 : "=r"(r[0]), "=r"(r[1]), "=r"(r[2]), "=r"(r[3]) : "r"(addr));
}
__device__ __forceinline__ void mma_bf16(float* c, const uint32_t* a, uint32_t b0, uint32_t b1) {
    asm volatile("mma.sync.aligned.m16n8k16.row.col.f32.bf16.bf16.f32 "
                 "{%0,%1,%2,%3}, {%4,%5,%6,%7}, {%8,%9}, {%0,%1,%2,%3};"
                 : "+f"(c[0]), "+f"(c[1]), "+f"(c[2]), "+f"(c[3])
                 : "r"(a[0]), "r"(a[1]), "r"(a[2]), "r"(a[3]), "r"(b0), "r"(b1));
}
__device__ __forceinline__ float lrelu(float v) { return v > 0.f ? v : 0.2f * v; }

// ============================================================================
// Tensor-core GEMM (mma.sync bf16, hi/lo 3-product split) + fused attn logits.
// ============================================================================
template<int K, int NTOT, int CHEAD>
__global__ __launch_bounds__(256, 2) void gemm_mma(
    const __nv_bfloat16* __restrict__ Ahi, const __nv_bfloat16* __restrict__ Alo,
    const __nv_bfloat16* __restrict__ Bhi, const __nv_bfloat16* __restrict__ Blo,
    float* __restrict__ C,
    const float* __restrict__ attsrc, const float* __restrict__ attdst,
    float* __restrict__ asrc, float* __restrict__ adst, int M)
{
    __shared__ __align__(16) __nv_bfloat16 sAh[128 * 32];
    __shared__ __align__(16) __nv_bfloat16 sAl[128 * 32];
    __shared__ __align__(16) __nv_bfloat16 sBh[128 * 32];
    __shared__ __align__(16) __nv_bfloat16 sBl[128 * 32];
    __shared__ float sAtt[2][128];
    __shared__ float sRed[2][128][2];

    const int tid = threadIdx.x;
    const int lane = tid & 31;
    const int wid = tid >> 5;
    const int wr = wid & 3;
    const int wc = wid >> 2;
    const int m0 = blockIdx.x * 128;
    const int n0 = blockIdx.y * 128;

    for (int i = tid; i < 128; i += 256) {
        sAtt[0][i] = attsrc[n0 + i];
        sAtt[1][i] = attdst[n0 + i];
    }

    const uint32_t sAhB = smem_u32(sAh), sAlB = smem_u32(sAl);
    const uint32_t sBhB = smem_u32(sBh), sBlB = smem_u32(sBl);

    float acc[2][8][4];
#pragma unroll
    for (int i = 0; i < 2; i++)
#pragma unroll
        for (int j = 0; j < 8; j++)
#pragma unroll
            for (int l = 0; l < 4; l++) acc[i][j][l] = 0.f;

    const int a_row = wr * 32 + (lane & 7) + ((lane >> 3) & 1) * 8;
    const int a_chA = lane >> 4;
    const int b_row = wc * 64 + (lane & 7) + (lane >> 4) * 8;
    const int b_chB = (lane >> 3) & 1;

    for (int ks = 0; ks < K / 32; ks++) {
#pragma unroll
        for (int j = 0; j < 2; j++) {
            int idx = tid + j * 256;
            int row = idx >> 2, ch = idx & 3;
            uint32_t soff = row * 64 + ((ch ^ (row & 3)) << 4);
            int grA = m0 + row;
            size_t gofs = (size_t)grA * K + ks * 32 + ch * 8;
            uint4 va = make_uint4(0u, 0u, 0u, 0u), vb = va;
            if (grA < M) { va = *(const uint4*)(Ahi + gofs); vb = *(const uint4*)(Alo + gofs); }
            *(uint4*)((char*)sAh + soff) = va;
            *(uint4*)((char*)sAl + soff) = vb;
            size_t gofsB = (size_t)(n0 + row) * K + ks * 32 + ch * 8;
            *(uint4*)((char*)sBh + soff) = *(const uint4*)(Bhi + gofsB);
            *(uint4*)((char*)sBl + soff) = *(const uint4*)(Blo + gofsB);
        }
        __syncthreads();

#pragma unroll
        for (int k16 = 0; k16 < 2; k16++) {
            uint32_t ah[2][4], al[2][4];
#pragma unroll
            for (int mt = 0; mt < 2; mt++) {
                int row = a_row + mt * 16;
                int ch = k16 * 2 + a_chA;
                uint32_t off = row * 64 + ((ch ^ (row & 3)) << 4);
                ldsm4(ah[mt], sAhB + off);
                ldsm4(al[mt], sAlB + off);
            }
#pragma unroll
            for (int ntg = 0; ntg < 4; ntg++) {
                int row = b_row + ntg * 16;
                int ch = k16 * 2 + b_chB;
                uint32_t off = row * 64 + ((ch ^ (row & 3)) << 4);
                uint32_t bh[4], bl[4];
                ldsm4(bh, sBhB + off);
                ldsm4(bl, sBlB + off);
#pragma unroll
                for (int mt = 0; mt < 2; mt++) {
                    mma_bf16(acc[mt][ntg * 2 + 0], ah[mt], bh[0], bh[1]);
                    mma_bf16(acc[mt][ntg * 2 + 0], al[mt], bh[0], bh[1]);
                    mma_bf16(acc[mt][ntg * 2 + 0], ah[mt], bl[0], bl[1]);
                    mma_bf16(acc[mt][ntg * 2 + 1], ah[mt], bh[2], bh[3]);
                    mma_bf16(acc[mt][ntg * 2 + 1], al[mt], bh[2], bh[3]);
                    mma_bf16(acc[mt][ntg * 2 + 1], ah[mt], bl[2], bl[3]);
                }
            }
        }
        __syncthreads();
    }

    float pss[2][2] = {}, psd[2][2] = {};
#pragma unroll
    for (int mt = 0; mt < 2; mt++) {
        int rloc = wr * 32 + mt * 16 + (lane >> 2);
        int grow0 = m0 + rloc, grow1 = grow0 + 8;
#pragma unroll
        for (int nt = 0; nt < 8; nt++) {
            int cl = wc * 64 + nt * 8 + (lane & 3) * 2;
            float a0s = sAtt[0][cl], a1s = sAtt[0][cl + 1];
            float a0d = sAtt[1][cl], a1d = sAtt[1][cl + 1];
            float c0 = acc[mt][nt][0], c1 = acc[mt][nt][1];
            float c2 = acc[mt][nt][2], c3 = acc[mt][nt][3];
            pss[mt][0] += c0 * a0s + c1 * a1s;  psd[mt][0] += c0 * a0d + c1 * a1d;
            pss[mt][1] += c2 * a0s + c3 * a1s;  psd[mt][1] += c2 * a0d + c3 * a1d;
            if (grow0 < M) *(float2*)&C[(size_t)grow0 * NTOT + n0 + cl] = make_float2(c0, c1);
            if (grow1 < M) *(float2*)&C[(size_t)grow1 * NTOT + n0 + cl] = make_float2(c2, c3);
        }
    }
#pragma unroll
    for (int mt = 0; mt < 2; mt++)
#pragma unroll
        for (int h8 = 0; h8 < 2; h8++) {
            float vs = pss[mt][h8], vd = psd[mt][h8];
            vs += __shfl_xor_sync(0xffffffffu, vs, 1); vs += __shfl_xor_sync(0xffffffffu, vs, 2);
            vd += __shfl_xor_sync(0xffffffffu, vd, 1); vd += __shfl_xor_sync(0xffffffffu, vd, 2);
            if ((lane & 3) == 0) {
                int r = wr * 32 + mt * 16 + h8 * 8 + (lane >> 2);
                sRed[wc][r][0] = vs;
                sRed[wc][r][1] = vd;
            }
        }
    __syncthreads();
    for (int r = tid; r < 128; r += 256) {
        int node = m0 + r;
        if (node >= M) continue;
        if (CHEAD == 128) {
            int h = n0 >> 7;
            asrc[node * 2 + h] = sRed[0][r][0] + sRed[1][r][0];
            adst[node * 2 + h] = sRed[0][r][1] + sRed[1][r][1];
        } else {
            asrc[node * 2 + 0] = sRed[0][r][0];  adst[node * 2 + 0] = sRed[0][r][1];
            asrc[node * 2 + 1] = sRed[1][r][0];  adst[node * 2 + 1] = sRed[1][r][1];
        }
    }
}

// ---------------- hi/lo split + prep ----------------
__device__ __forceinline__ void split2(float v, __nv_bfloat16& h, __nv_bfloat16& l) {
    h = __float2bfloat16(v);
    l = __float2bfloat16(v - __bfloat162float(h));
}

__global__ void split_x_k(const float* __restrict__ x,
                          __nv_bfloat16* __restrict__ xh, __nv_bfloat16* __restrict__ xl) {
    size_t i = (size_t)blockIdx.x * blockDim.x + threadIdx.x;
    if (i >= (size_t)N_NODES * IN_CH) return;
    split2(x[i], xh[i], xl[i]);
}

__global__ void prep_k(const float* __restrict__ W1,
                       const float* __restrict__ Wmu, const float* __restrict__ Wls,
                       const float* __restrict__ asmu, const float* __restrict__ asls,
                       const float* __restrict__ admu, const float* __restrict__ adls,
                       __nv_bfloat16* __restrict__ W1Th, __nv_bfloat16* __restrict__ W1Tl,
                       __nv_bfloat16* __restrict__ WcTh, __nv_bfloat16* __restrict__ WcTl,
                       float* __restrict__ a2s, float* __restrict__ a2d) {
    int i = blockIdx.x * blockDim.x + threadIdx.x;
    if (i < 256 * 128) {
        int n = i >> 7, k = i & 127;
        split2(W1[k * 256 + n], W1Th[i], W1Tl[i]);
    } else if (i < 2 * 256 * 128) {
        int j = i - 256 * 128;
        int n = j >> 8, k = j & 255;
        float w = (n < 64) ? Wmu[k * 64 + n] : Wls[k * 64 + (n - 64)];
        split2(w, WcTh[j], WcTl[j]);
    } else if (i < 2 * 256 * 128 + 128) {
        int j = i - 2 * 256 * 128;
        a2s[j] = (j < 64) ? asmu[j] : asls[j - 64];
    } else if (i < 2 * 256 * 128 + 256) {
        int j = i - 2 * 256 * 128 - 128;
        a2d[j] = (j < 64) ? admu[j] : adls[j - 64];
    }
}

// ---------------- CSR build ----------------
__global__ void csr_count_k(const int* __restrict__ ei, int* __restrict__ deg) {
    int e = blockIdx.x * blockDim.x + threadIdx.x;
    if (e >= E_TOT) return;
    int d = (e < E_EDGES) ? ei[E_EDGES + e] : e - E_EDGES;
    atomicAdd(&deg[d], 1);
}

__global__ void scanA_k(const int* __restrict__ deg, int* __restrict__ ptr,
                        int* __restrict__ blockSum) {
    __shared__ int sh[256];
    int i = blockIdx.x * 256 + threadIdx.x;
    int v = (i < N_NODES) ? deg[i] : 0;
    sh[threadIdx.x] = v;
    __syncthreads();
#pragma unroll
    for (int off = 1; off < 256; off <<= 1) {
        int t = (threadIdx.x >= off) ? sh[threadIdx.x - off] : 0;
        __syncthreads();
        sh[threadIdx.x] += t;
        __syncthreads();
    }
    if (i < N_NODES) ptr[i] = sh[threadIdx.x] - v;   // exclusive, local
    if (threadIdx.x == 255) blockSum[blockIdx.x] = sh[255];
}

__global__ void scanB_k(const int* __restrict__ blockSum, int* __restrict__ blockOff) {
    __shared__ int sh[256];
    int v = (threadIdx.x < NBLK) ? blockSum[threadIdx.x] : 0;
    sh[threadIdx.x] = v;
    __syncthreads();
#pragma unroll
    for (int off = 1; off < 256; off <<= 1) {
        int t = (threadIdx.x >= off) ? sh[threadIdx.x - off] : 0;
        __syncthreads();
        sh[threadIdx.x] += t;
        __syncthreads();
    }
    if (threadIdx.x < NBLK) blockOff[threadIdx.x] = sh[threadIdx.x] - v;
}

__global__ void scanC_k(int* __restrict__ ptr, const int* __restrict__ blockOff) {
    int i = blockIdx.x * blockDim.x + threadIdx.x;
    if (i < N_NODES) ptr[i] += blockOff[i >> 8];
    if (i == 0) ptr[N_NODES] = E_TOT;
}

__global__ void csr_fill_k(const int* __restrict__ ei, int* __restrict__ cursor,
                           int* __restrict__ csrsrc) {
    int e = blockIdx.x * blockDim.x + threadIdx.x;
    if (e >= E_TOT) return;
    int s, d;
    if (e < E_EDGES) { s = ei[e]; d = ei[E_EDGES + e]; }
    else             { s = d = e - E_EDGES; }
    int pos = atomicAdd(&cursor[d], 1);
    csrsrc[pos] = s;
}

// ============================================================================
// Layer-1 fused softmax + aggregate (+bias, ELU, bf16 split). One warp/node.
// ============================================================================
__global__ __launch_bounds__(256) void agg1_k(
    const float* __restrict__ H1, const float* __restrict__ A1s, const float* __restrict__ A1d,
    const int* __restrict__ ptr, const int* __restrict__ csrsrc,
    const float* __restrict__ b1,
    __nv_bfloat16* __restrict__ h2h, __nv_bfloat16* __restrict__ h2l)
{
    int node = (blockIdx.x * 256 + threadIdx.x) >> 5;
    if (node >= N_NODES) return;
    int lane = threadIdx.x & 31;
    int p0 = ptr[node], deg = ptr[node + 1] - p0;
    float2 ad = *(const float2*)&A1d[node * 2];

    // pass 1: max
    float m0 = -1e30f, m1 = -1e30f;
    for (int base = 0; base < deg; base += 32) {
        int e = base + lane;
        if (e < deg) {
            int s = csrsrc[p0 + e];
            float2 as = *(const float2*)&A1s[s * 2];
            m0 = fmaxf(m0, lrelu(as.x + ad.x));
            m1 = fmaxf(m1, lrelu(as.y + ad.y));
        }
    }
#pragma unroll
    for (int o = 16; o; o >>= 1) {
        m0 = fmaxf(m0, __shfl_xor_sync(0xffffffffu, m0, o));
        m1 = fmaxf(m1, __shfl_xor_sync(0xffffffffu, m1, o));
    }
    // pass 2: denom
    float d0 = 0.f, d1 = 0.f;
    for (int base = 0; base < deg; base += 32) {
        int e = base + lane;
        if (e < deg) {
            int s = csrsrc[p0 + e];
            float2 as = *(const float2*)&A1s[s * 2];
            d0 += __expf(lrelu(as.x + ad.x) - m0);
            d1 += __expf(lrelu(as.y + ad.y) - m1);
        }
    }
#pragma unroll
    for (int o = 16; o; o >>= 1) {
        d0 += __shfl_xor_sync(0xffffffffu, d0, o);
        d1 += __shfl_xor_sync(0xffffffffu, d1, o);
    }
    float inv0 = 1.f / (d0 + 1e-16f), inv1 = 1.f / (d1 + 1e-16f);

    // pass 3: weighted gather-accumulate
    float a0x = 0.f, a0y = 0.f, a0z = 0.f, a0w = 0.f;
    float a1x = 0.f, a1y = 0.f, a1z = 0.f, a1w = 0.f;
#pragma unroll 2
    for (int e = 0; e < deg; e++) {
        int s = csrsrc[p0 + e];
        float2 as = *(const float2*)&A1s[s * 2];
        float al0 = __expf(lrelu(as.x + ad.x) - m0) * inv0;
        float al1 = __expf(lrelu(as.y + ad.y) - m1) * inv1;
        const float4* row = (const float4*)(H1 + (size_t)s * H1C);
        float4 r0 = row[lane], r1 = row[32 + lane];
        a0x += al0 * r0.x; a0y += al0 * r0.y; a0z += al0 * r0.z; a0w += al0 * r0.w;
        a1x += al1 * r1.x; a1y += al1 * r1.y; a1z += al1 * r1.z; a1w += al1 * r1.w;
    }

    // epilogue: + bias, ELU, hi/lo split
    int c0 = lane * 4;
    float4 bb0 = *(const float4*)&b1[c0];
    float4 bb1 = *(const float4*)&b1[128 + c0];
    float v[8] = {a0x + bb0.x, a0y + bb0.y, a0z + bb0.z, a0w + bb0.w,
                  a1x + bb1.x, a1y + bb1.y, a1z + bb1.z, a1w + bb1.w};
    __nv_bfloat16 hh[8], ll[8];
#pragma unroll
    for (int i = 0; i < 8; i++) {
        float e = v[i] > 0.f ? v[i] : expm1f(v[i]);
        split2(e, hh[i], ll[i]);
    }
    size_t o0 = (size_t)node * H1C + c0;
    size_t o1 = o0 + 128;
    *(__nv_bfloat162*)&h2h[o0]     = __nv_bfloat162(hh[0], hh[1]);
    *(__nv_bfloat162*)&h2h[o0 + 2] = __nv_bfloat162(hh[2], hh[3]);
    *(__nv_bfloat162*)&h2h[o1]     = __nv_bfloat162(hh[4], hh[5]);
    *(__nv_bfloat162*)&h2h[o1 + 2] = __nv_bfloat162(hh[6], hh[7]);
    *(__nv_bfloat162*)&h2l[o0]     = __nv_bfloat162(ll[0], ll[1]);
    *(__nv_bfloat162*)&h2l[o0 + 2] = __nv_bfloat162(ll[2], ll[3]);
    *(__nv_bfloat162*)&h2l[o1]     = __nv_bfloat162(ll[4], ll[5]);
    *(__nv_bfloat162*)&h2l[o1 + 2] = __nv_bfloat162(ll[6], ll[7]);
}

// ============================================================================
// Layer-2 fused softmax + aggregate (+bias). One warp/node; lane h = c>=64.
// ============================================================================
__global__ __launch_bounds__(256) void agg2_k(
    const float* __restrict__ G, const float* __restrict__ A2s, const float* __restrict__ A2d,
    const int* __restrict__ ptr, const int* __restrict__ csrsrc,
    const float* __restrict__ bmu, const float* __restrict__ bls,
    float* __restrict__ out)
{
    int node = (blockIdx.x * 256 + threadIdx.x) >> 5;
    if (node >= N_NODES) return;
    int lane = threadIdx.x & 31;
    int p0 = ptr[node], deg = ptr[node + 1] - p0;
    float2 ad = *(const float2*)&A2d[node * 2];

    float m0 = -1e30f, m1 = -1e30f;
    for (int base = 0; base < deg; base += 32) {
        int e = base + lane;
        if (e < deg) {
            int s = csrsrc[p0 + e];
            float2 as = *(const float2*)&A2s[s * 2];
            m0 = fmaxf(m0, lrelu(as.x + ad.x));
            m1 = fmaxf(m1, lrelu(as.y + ad.y));
        }
    }
#pragma unroll
    for (int o = 16; o; o >>= 1) {
        m0 = fmaxf(m0, __shfl_xor_sync(0xffffffffu, m0, o));
        m1 = fmaxf(m1, __shfl_xor_sync(0xffffffffu, m1, o));
    }
    float d0 = 0.f, d1 = 0.f;
    for (int base = 0; base < deg; base += 32) {
        int e = base + lane;
        if (e < deg) {
            int s = csrsrc[p0 + e];
            float2 as = *(const float2*)&A2s[s * 2];
            d0 += __expf(lrelu(as.x + ad.x) - m0);
            d1 += __expf(lrelu(as.y + ad.y) - m1);
        }
    }
#pragma unroll
    for (int o = 16; o; o >>= 1) {
        d0 += __shfl_xor_sync(0xffffffffu, d0, o);
        d1 += __shfl_xor_sync(0xffffffffu, d1, o);
    }
    float inv0 = 1.f / (d0 + 1e-16f), inv1 = 1.f / (d1 + 1e-16f);

    int h = lane >> 4;   // lane*4 channels: c in [0,64) -> mu, [64,128) -> ls
    float ax = 0.f, ay = 0.f, az = 0.f, aw = 0.f;
#pragma unroll 2
    for (int e = 0; e < deg; e++) {
        int s = csrsrc[p0 + e];
        float2 as = *(const float2*)&A2s[s * 2];
        float al0 = __expf(lrelu(as.x + ad.x) - m0) * inv0;
        float al1 = __expf(lrelu(as.y + ad.y) - m1) * inv1;
        float al = h ? al1 : al0;
        float4 r = ((const float4*)(G + (size_t)s * 128))[lane];
        ax += al * r.x; ay += al * r.y; az += al * r.z; aw += al * r.w;
    }
    int cl = (lane & 15) * 4;   // channel within head
    float4 bb = h ? *(const float4*)&bls[cl] : *(const float4*)&bmu[cl];
    float* dp = out + (size_t)h * N_NODES * OUTC + (size_t)node * OUTC + cl;
    *(float4*)dp = make_float4(ax + bb.x, ay + bb.y, az + bb.z, aw + bb.w);
}

// ---------------- launch ----------------
extern "C" void kernel_launch(void* const* d_in, const int* in_sizes, int n_in,
                              void* d_out, int out_size) {
    const float* x        = (const float*)d_in[0];
    const int*   ei       = (const int*)  d_in[1];
    const float* W1       = (const float*)d_in[2];
    const float* att_src1 = (const float*)d_in[3];
    const float* att_dst1 = (const float*)d_in[4];
    const float* b1       = (const float*)d_in[5];
    const float* W_mu     = (const float*)d_in[6];
    const float* as_mu    = (const float*)d_in[7];
    const float* ad_mu    = (const float*)d_in[8];
    const float* b_mu     = (const float*)d_in[9];
    const float* W_ls     = (const float*)d_in[10];
    const float* as_ls    = (const float*)d_in[11];
    const float* ad_ls    = (const float*)d_in[12];
    const float* b_ls     = (const float*)d_in[13];
    float* out = (float*)d_out;

    float *H1, *Gcat, *A1s, *A1d, *A2s, *A2d, *a2s, *a2d;
    __nv_bfloat16 *Xhi, *Xlo, *H2hi, *H2lo, *W1Th, *W1Tl, *WcTh, *WcTl;
    int *deg, *ptr, *cursor, *csrsrc, *blockSum, *blockOff;
    cudaGetSymbolAddress((void**)&H1,   g_H1);
    cudaGetSymbolAddress((void**)&Gcat, g_Gcat);
    cudaGetSymbolAddress((void**)&A1s,  g_A1src);
    cudaGetSymbolAddress((void**)&A1d,  g_A1dst);
    cudaGetSymbolAddress((void**)&A2s,  g_A2src);
    cudaGetSymbolAddress((void**)&A2d,  g_A2dst);
    cudaGetSymbolAddress((void**)&a2s,  g_att2src);
    cudaGetSymbolAddress((void**)&a2d,  g_att2dst);
    cudaGetSymbolAddress((void**)&Xhi,  g_Xhi);
    cudaGetSymbolAddress((void**)&Xlo,  g_Xlo);
    cudaGetSymbolAddress((void**)&H2hi, g_H2hi);
    cudaGetSymbolAddress((void**)&H2lo, g_H2lo);
    cudaGetSymbolAddress((void**)&W1Th, g_W1T_hi);
    cudaGetSymbolAddress((void**)&W1Tl, g_W1T_lo);
    cudaGetSymbolAddress((void**)&WcTh, g_WcT_hi);
    cudaGetSymbolAddress((void**)&WcTl, g_WcT_lo);
    cudaGetSymbolAddress((void**)&deg,    g_deg);
    cudaGetSymbolAddress((void**)&ptr,    g_ptr);
    cudaGetSymbolAddress((void**)&cursor, g_cursor);
    cudaGetSymbolAddress((void**)&csrsrc, g_csrsrc);
    cudaGetSymbolAddress((void**)&blockSum, g_blockSum);
    cudaGetSymbolAddress((void**)&blockOff, g_blockOff);

    // ---- CSR build (graph shared by both layers) ----
    cudaMemsetAsync(deg, 0, N_NODES * sizeof(int));
    csr_count_k<<<(E_TOT + 255) / 256, 256>>>(ei, deg);
    scanA_k<<<NBLK, 256>>>(deg, ptr, blockSum);
    scanB_k<<<1, 256>>>(blockSum, blockOff);
    scanC_k<<<NBLK, 256>>>(ptr, blockOff);
    cudaMemcpyAsync(cursor, ptr, N_NODES * sizeof(int), cudaMemcpyDeviceToDevice);
    csr_fill_k<<<(E_TOT + 255) / 256, 256>>>(ei, cursor, csrsrc);

    // ---- data prep ----
    split_x_k<<<((size_t)N_NODES * IN_CH + 255) / 256, 256>>>(x, Xhi, Xlo);
    prep_k<<<(2 * 256 * 128 + 256 + 255) / 256, 256>>>(W1, W_mu, W_ls, as_mu, as_ls, ad_mu, ad_ls,
                                                       W1Th, W1Tl, WcTh, WcTl, a2s, a2d);

    const int gx = (N_NODES + 127) / 128;
    const int aggBlocks = (N_NODES * 32 + 255) / 256;

    // ---- layer 1 ----
    gemm_mma<128, 256, 128><<<dim3(gx, 2), 256>>>(
        Xhi, Xlo, W1Th, W1Tl, H1, att_src1, att_dst1, A1s, A1d, N_NODES);
    agg1_k<<<aggBlocks, 256>>>(H1, A1s, A1d, ptr, csrsrc, b1, H2hi, H2lo);

    // ---- layer 2 ----
    gemm_mma<256, 128, 64><<<dim3(gx, 1), 256>>>(
        H2hi, H2lo, WcTh, WcTl, Gcat, a2s, a2d, A2s, A2d, N_NODES);
    agg2_k<<<aggBlocks, 256>>>(Gcat, A2s, A2d, ptr, csrsrc, b_mu, b_ls, out);
}

// round 5
// speedup vs baseline: 2.4817x; 1.1011x over previous
#include <cuda_runtime.h>
#include <cuda_bf16.h>
#include <math.h>
#include <stdint.h>

#define N_NODES 50000
#define IN_CH   128
#define E_EDGES 400000
#define E_TOT   (E_EDGES + N_NODES)   // with self loops
#define HID     128                   // per-head channels of conv1
#define H1C     256                   // HEADS*HID
#define OUTC    64
#define NBLK    ((N_NODES + 255) / 256)   // scan blocks

// ---------------- scratch (device globals: allocation-free) ----------------
__device__ float g_H1  [(size_t)N_NODES * H1C];   // x @ W1 (fp32)
__device__ float g_Gcat[(size_t)N_NODES * 128];   // [h2 @ W_mu | h2 @ W_ls]
__device__ __nv_bfloat16 g_H2hi[(size_t)N_NODES * H1C];
__device__ __nv_bfloat16 g_H2lo[(size_t)N_NODES * H1C];
__device__ __nv_bfloat16 g_W1T_hi[256 * 128];   // [N=256 rows][K=128]
__device__ __nv_bfloat16 g_W1T_lo[256 * 128];
__device__ __nv_bfloat16 g_WcT_hi[128 * 256];   // [N=128 rows][K=256]
__device__ __nv_bfloat16 g_WcT_lo[128 * 256];
__device__ float g_A1src[N_NODES * 2];
__device__ float g_A1dst[N_NODES * 2];
__device__ float g_A2src[N_NODES * 2];
__device__ float g_A2dst[N_NODES * 2];
__device__ float g_att2src[128];   // [as_mu(64) | as_ls(64)]
__device__ float g_att2dst[128];   // [ad_mu(64) | ad_ls(64)]
// CSR
__device__ int g_deg[N_NODES];
__device__ int g_ptr[N_NODES + 1];
__device__ int g_cursor[N_NODES];
__device__ int g_csrsrc[E_TOT];
__device__ int g_blockSum[NBLK];
__device__ int g_blockOff[NBLK];

// ---------------- low-level helpers ----------------
__device__ __forceinline__ uint32_t smem_u32(const void* p) {
    uint32_t a;
    asm("{ .reg .u64 t; cvta.to.shared.u64 t, %1; cvt.u32.u64 %0, t; }" : "=r"(a) : "l"(p));
    return a;
}
__device__ __forceinline__ void ldsm4(uint32_t* r, uint32_t addr) {
    asm volatile("ldmatrix.sync.aligned.m8n8.x4.shared.b16 {%0,%1,%2,%3}, [%4];"
                 : "=r"(r[0]), "=r"(r[1]), "=r"(r[2]), "=r"(r[3]) : "r"(addr));
}
__device__ __forceinline__ void mma_bf16(float* c, const uint32_t* a, uint32_t b0, uint32_t b1) {
    asm volatile("mma.sync.aligned.m16n8k16.row.col.f32.bf16.bf16.f32 "
                 "{%0,%1,%2,%3}, {%4,%5,%6,%7}, {%8,%9}, {%0,%1,%2,%3};"
                 : "+f"(c[0]), "+f"(c[1]), "+f"(c[2]), "+f"(c[3])
                 : "r"(a[0]), "r"(a[1]), "r"(a[2]), "r"(a[3]), "r"(b0), "r"(b1));
}
__device__ __forceinline__ float lrelu(float v) { return v > 0.f ? v : 0.2f * v; }
__device__ __forceinline__ void split2(float v, __nv_bfloat16& h, __nv_bfloat16& l) {
    h = __float2bfloat16(v);
    l = __float2bfloat16(v - __bfloat162float(h));
}

// ============================================================================
// Tensor-core GEMM (mma.sync bf16, hi/lo 3-product split) + fused attn logits.
// Single k-sweep: each chunk loaded ONCE; all 3 products issued per chunk.
// If AFP32, A is fp32 and hi/lo-split in registers during the smem store.
// C[M,NTOT] = A[M,K] @ B^T; B stored [NTOT][K]. CTA tile 128x128, 8 warps.
// ============================================================================
template<int K, int NTOT, int CHEAD, bool AFP32>
__global__ __launch_bounds__(256, 2) void gemm_mma(
    const float* __restrict__ Afp,
    const __nv_bfloat16* __restrict__ Ahi, const __nv_bfloat16* __restrict__ Alo,
    const __nv_bfloat16* __restrict__ Bhi, const __nv_bfloat16* __restrict__ Blo,
    float* __restrict__ C,
    const float* __restrict__ attsrc, const float* __restrict__ attdst,
    float* __restrict__ asrc, float* __restrict__ adst, int M)
{
    __shared__ __align__(16) __nv_bfloat16 sAh[128 * 32];
    __shared__ __align__(16) __nv_bfloat16 sAl[128 * 32];
    __shared__ __align__(16) __nv_bfloat16 sBh[128 * 32];
    __shared__ __align__(16) __nv_bfloat16 sBl[128 * 32];
    __shared__ float sAtt[2][128];
    __shared__ float sRed[2][128][2];

    const int tid = threadIdx.x;
    const int lane = tid & 31;
    const int wid = tid >> 5;
    const int wr = wid & 3;
    const int wc = wid >> 2;
    const int m0 = blockIdx.x * 128;
    const int n0 = blockIdx.y * 128;

    for (int i = tid; i < 128; i += 256) {
        sAtt[0][i] = attsrc[n0 + i];
        sAtt[1][i] = attdst[n0 + i];
    }

    const uint32_t sAhB = smem_u32(sAh), sAlB = smem_u32(sAl);
    const uint32_t sBhB = smem_u32(sBh), sBlB = smem_u32(sBl);

    float acc[2][8][4];
#pragma unroll
    for (int i = 0; i < 2; i++)
#pragma unroll
        for (int j = 0; j < 8; j++)
#pragma unroll
            for (int l = 0; l < 4; l++) acc[i][j][l] = 0.f;

    const int a_row = wr * 32 + (lane & 7) + ((lane >> 3) & 1) * 8;
    const int a_chA = lane >> 4;
    const int b_row = wc * 64 + (lane & 7) + (lane >> 4) * 8;
    const int b_chB = (lane >> 3) & 1;

    for (int ks = 0; ks < K / 32; ks++) {
        // ---- A tile -> smem ----
        if (AFP32) {
            // 128 rows x 32 fp32 = 1024 float4 units; split to hi/lo in regs
#pragma unroll
            for (int j = 0; j < 4; j++) {
                int idx = tid + j * 256;
                int row = idx >> 3, cg = idx & 7;       // cg: group of 4 floats
                int grA = m0 + row;
                float4 v = make_float4(0.f, 0.f, 0.f, 0.f);
                if (grA < M) v = *(const float4*)(Afp + (size_t)grA * K + ks * 32 + cg * 4);
                __nv_bfloat16 h0, h1, h2, h3, l0, l1, l2, l3;
                split2(v.x, h0, l0); split2(v.y, h1, l1);
                split2(v.z, h2, l2); split2(v.w, h3, l3);
                uint32_t soff = row * 64 + (((cg >> 1) ^ (row & 3)) << 4) + (cg & 1) * 8;
                __nv_bfloat162 hp0(h0, h1), hp1(h2, h3), lp0(l0, l1), lp1(l2, l3);
                *(uint2*)((char*)sAh + soff) = make_uint2(*(uint32_t*)&hp0, *(uint32_t*)&hp1);
                *(uint2*)((char*)sAl + soff) = make_uint2(*(uint32_t*)&lp0, *(uint32_t*)&lp1);
            }
        } else {
#pragma unroll
            for (int j = 0; j < 2; j++) {
                int idx = tid + j * 256;
                int row = idx >> 2, ch = idx & 3;
                uint32_t soff = row * 64 + ((ch ^ (row & 3)) << 4);
                int grA = m0 + row;
                size_t gofs = (size_t)grA * K + ks * 32 + ch * 8;
                uint4 va = make_uint4(0u, 0u, 0u, 0u), vb = va;
                if (grA < M) { va = *(const uint4*)(Ahi + gofs); vb = *(const uint4*)(Alo + gofs); }
                *(uint4*)((char*)sAh + soff) = va;
                *(uint4*)((char*)sAl + soff) = vb;
            }
        }
        // ---- B tile -> smem ----
#pragma unroll
        for (int j = 0; j < 2; j++) {
            int idx = tid + j * 256;
            int row = idx >> 2, ch = idx & 3;
            uint32_t soff = row * 64 + ((ch ^ (row & 3)) << 4);
            size_t gofsB = (size_t)(n0 + row) * K + ks * 32 + ch * 8;
            *(uint4*)((char*)sBh + soff) = *(const uint4*)(Bhi + gofsB);
            *(uint4*)((char*)sBl + soff) = *(const uint4*)(Blo + gofsB);
        }
        __syncthreads();

#pragma unroll
        for (int k16 = 0; k16 < 2; k16++) {
            uint32_t ah[2][4], al[2][4];
#pragma unroll
            for (int mt = 0; mt < 2; mt++) {
                int row = a_row + mt * 16;
                int ch = k16 * 2 + a_chA;
                uint32_t off = row * 64 + ((ch ^ (row & 3)) << 4);
                ldsm4(ah[mt], sAhB + off);
                ldsm4(al[mt], sAlB + off);
            }
#pragma unroll
            for (int ntg = 0; ntg < 4; ntg++) {
                int row = b_row + ntg * 16;
                int ch = k16 * 2 + b_chB;
                uint32_t off = row * 64 + ((ch ^ (row & 3)) << 4);
                uint32_t bh[4], bl[4];
                ldsm4(bh, sBhB + off);
                ldsm4(bl, sBlB + off);
#pragma unroll
                for (int mt = 0; mt < 2; mt++) {
                    mma_bf16(acc[mt][ntg * 2 + 0], ah[mt], bh[0], bh[1]);
                    mma_bf16(acc[mt][ntg * 2 + 0], al[mt], bh[0], bh[1]);
                    mma_bf16(acc[mt][ntg * 2 + 0], ah[mt], bl[0], bl[1]);
                    mma_bf16(acc[mt][ntg * 2 + 1], ah[mt], bh[2], bh[3]);
                    mma_bf16(acc[mt][ntg * 2 + 1], al[mt], bh[2], bh[3]);
                    mma_bf16(acc[mt][ntg * 2 + 1], ah[mt], bl[2], bl[3]);
                }
            }
        }
        __syncthreads();
    }

    float pss[2][2] = {}, psd[2][2] = {};
#pragma unroll
    for (int mt = 0; mt < 2; mt++) {
        int rloc = wr * 32 + mt * 16 + (lane >> 2);
        int grow0 = m0 + rloc, grow1 = grow0 + 8;
#pragma unroll
        for (int nt = 0; nt < 8; nt++) {
            int cl = wc * 64 + nt * 8 + (lane & 3) * 2;
            float a0s = sAtt[0][cl], a1s = sAtt[0][cl + 1];
            float a0d = sAtt[1][cl], a1d = sAtt[1][cl + 1];
            float c0 = acc[mt][nt][0], c1 = acc[mt][nt][1];
            float c2 = acc[mt][nt][2], c3 = acc[mt][nt][3];
            pss[mt][0] += c0 * a0s + c1 * a1s;  psd[mt][0] += c0 * a0d + c1 * a1d;
            pss[mt][1] += c2 * a0s + c3 * a1s;  psd[mt][1] += c2 * a0d + c3 * a1d;
            if (grow0 < M) *(float2*)&C[(size_t)grow0 * NTOT + n0 + cl] = make_float2(c0, c1);
            if (grow1 < M) *(float2*)&C[(size_t)grow1 * NTOT + n0 + cl] = make_float2(c2, c3);
        }
    }
#pragma unroll
    for (int mt = 0; mt < 2; mt++)
#pragma unroll
        for (int h8 = 0; h8 < 2; h8++) {
            float vs = pss[mt][h8], vd = psd[mt][h8];
            vs += __shfl_xor_sync(0xffffffffu, vs, 1); vs += __shfl_xor_sync(0xffffffffu, vs, 2);
            vd += __shfl_xor_sync(0xffffffffu, vd, 1); vd += __shfl_xor_sync(0xffffffffu, vd, 2);
            if ((lane & 3) == 0) {
                int r = wr * 32 + mt * 16 + h8 * 8 + (lane >> 2);
                sRed[wc][r][0] = vs;
                sRed[wc][r][1] = vd;
            }
        }
    __syncthreads();
    for (int r = tid; r < 128; r += 256) {
        int node = m0 + r;
        if (node >= M) continue;
        if (CHEAD == 128) {
            int h = n0 >> 7;
            asrc[node * 2 + h] = sRed[0][r][0] + sRed[1][r][0];
            adst[node * 2 + h] = sRed[0][r][1] + sRed[1][r][1];
        } else {
            asrc[node * 2 + 0] = sRed[0][r][0];  adst[node * 2 + 0] = sRed[0][r][1];
            asrc[node * 2 + 1] = sRed[1][r][0];  adst[node * 2 + 1] = sRed[1][r][1];
        }
    }
}

// ---------------- prep: transposed hi/lo weights + att concat ----------------
__global__ void prep_k(const float* __restrict__ W1,
                       const float* __restrict__ Wmu, const float* __restrict__ Wls,
                       const float* __restrict__ asmu, const float* __restrict__ asls,
                       const float* __restrict__ admu, const float* __restrict__ adls,
                       __nv_bfloat16* __restrict__ W1Th, __nv_bfloat16* __restrict__ W1Tl,
                       __nv_bfloat16* __restrict__ WcTh, __nv_bfloat16* __restrict__ WcTl,
                       float* __restrict__ a2s, float* __restrict__ a2d) {
    int i = blockIdx.x * blockDim.x + threadIdx.x;
    if (i < 256 * 128) {
        int n = i >> 7, k = i & 127;
        split2(W1[k * 256 + n], W1Th[i], W1Tl[i]);
    } else if (i < 2 * 256 * 128) {
        int j = i - 256 * 128;
        int n = j >> 8, k = j & 255;
        float w = (n < 64) ? Wmu[k * 64 + n] : Wls[k * 64 + (n - 64)];
        split2(w, WcTh[j], WcTl[j]);
    } else if (i < 2 * 256 * 128 + 128) {
        int j = i - 2 * 256 * 128;
        a2s[j] = (j < 64) ? asmu[j] : asls[j - 64];
    } else if (i < 2 * 256 * 128 + 256) {
        int j = i - 2 * 256 * 128 - 128;
        a2d[j] = (j < 64) ? admu[j] : adls[j - 64];
    }
}

// ---------------- CSR build ----------------
__global__ void csr_count_k(const int* __restrict__ ei, int* __restrict__ deg) {
    int e = blockIdx.x * blockDim.x + threadIdx.x;
    if (e >= E_TOT) return;
    int d = (e < E_EDGES) ? ei[E_EDGES + e] : e - E_EDGES;
    atomicAdd(&deg[d], 1);
}

__global__ void scanA_k(const int* __restrict__ deg, int* __restrict__ ptr,
                        int* __restrict__ blockSum) {
    __shared__ int sh[256];
    int i = blockIdx.x * 256 + threadIdx.x;
    int v = (i < N_NODES) ? deg[i] : 0;
    sh[threadIdx.x] = v;
    __syncthreads();
#pragma unroll
    for (int off = 1; off < 256; off <<= 1) {
        int t = (threadIdx.x >= off) ? sh[threadIdx.x - off] : 0;
        __syncthreads();
        sh[threadIdx.x] += t;
        __syncthreads();
    }
    if (i < N_NODES) ptr[i] = sh[threadIdx.x] - v;   // exclusive, local
    if (threadIdx.x == 255) blockSum[blockIdx.x] = sh[255];
}

__global__ void scanB_k(const int* __restrict__ blockSum, int* __restrict__ blockOff) {
    __shared__ int sh[256];
    int v = (threadIdx.x < NBLK) ? blockSum[threadIdx.x] : 0;
    sh[threadIdx.x] = v;
    __syncthreads();
#pragma unroll
    for (int off = 1; off < 256; off <<= 1) {
        int t = (threadIdx.x >= off) ? sh[threadIdx.x - off] : 0;
        __syncthreads();
        sh[threadIdx.x] += t;
        __syncthreads();
    }
    if (threadIdx.x < NBLK) blockOff[threadIdx.x] = sh[threadIdx.x] - v;
}

__global__ void scanC_k(int* __restrict__ ptr, const int* __restrict__ blockOff,
                        int* __restrict__ cursor) {
    int i = blockIdx.x * blockDim.x + threadIdx.x;
    if (i < N_NODES) {
        int v = ptr[i] + blockOff[i >> 8];
        ptr[i] = v;
        cursor[i] = v;
    }
    if (i == 0) ptr[N_NODES] = E_TOT;
}

__global__ void csr_fill_k(const int* __restrict__ ei, int* __restrict__ cursor,
                           int* __restrict__ csrsrc) {
    int e = blockIdx.x * blockDim.x + threadIdx.x;
    if (e >= E_TOT) return;
    int s, d;
    if (e < E_EDGES) { s = ei[e]; d = ei[E_EDGES + e]; }
    else             { s = d = e - E_EDGES; }
    int pos = atomicAdd(&cursor[d], 1);
    csrsrc[pos] = s;
}

// ============================================================================
// Layer-1 fused softmax + aggregate (+bias, ELU, bf16 split). One warp/node.
// ============================================================================
__global__ __launch_bounds__(256) void agg1_k(
    const float* __restrict__ H1, const float* __restrict__ A1s, const float* __restrict__ A1d,
    const int* __restrict__ ptr, const int* __restrict__ csrsrc,
    const float* __restrict__ b1,
    __nv_bfloat16* __restrict__ h2h, __nv_bfloat16* __restrict__ h2l)
{
    int node = (blockIdx.x * 256 + threadIdx.x) >> 5;
    if (node >= N_NODES) return;
    int lane = threadIdx.x & 31;
    int p0 = ptr[node], deg = ptr[node + 1] - p0;
    float2 ad = *(const float2*)&A1d[node * 2];

    float m0 = -1e30f, m1 = -1e30f;
    for (int base = 0; base < deg; base += 32) {
        int e = base + lane;
        if (e < deg) {
            int s = csrsrc[p0 + e];
            float2 as = *(const float2*)&A1s[s * 2];
            m0 = fmaxf(m0, lrelu(as.x + ad.x));
            m1 = fmaxf(m1, lrelu(as.y + ad.y));
        }
    }
#pragma unroll
    for (int o = 16; o; o >>= 1) {
        m0 = fmaxf(m0, __shfl_xor_sync(0xffffffffu, m0, o));
        m1 = fmaxf(m1, __shfl_xor_sync(0xffffffffu, m1, o));
    }
    float d0 = 0.f, d1 = 0.f;
    for (int base = 0; base < deg; base += 32) {
        int e = base + lane;
        if (e < deg) {
            int s = csrsrc[p0 + e];
            float2 as = *(const float2*)&A1s[s * 2];
            d0 += __expf(lrelu(as.x + ad.x) - m0);
            d1 += __expf(lrelu(as.y + ad.y) - m1);
        }
    }
#pragma unroll
    for (int o = 16; o; o >>= 1) {
        d0 += __shfl_xor_sync(0xffffffffu, d0, o);
        d1 += __shfl_xor_sync(0xffffffffu, d1, o);
    }
    float inv0 = 1.f / (d0 + 1e-16f), inv1 = 1.f / (d1 + 1e-16f);

    float a0x = 0.f, a0y = 0.f, a0z = 0.f, a0w = 0.f;
    float a1x = 0.f, a1y = 0.f, a1z = 0.f, a1w = 0.f;
#pragma unroll 2
    for (int e = 0; e < deg; e++) {
        int s = csrsrc[p0 + e];
        float2 as = *(const float2*)&A1s[s * 2];
        float al0 = __expf(lrelu(as.x + ad.x) - m0) * inv0;
        float al1 = __expf(lrelu(as.y + ad.y) - m1) * inv1;
        const float4* row = (const float4*)(H1 + (size_t)s * H1C);
        float4 r0 = row[lane], r1 = row[32 + lane];
        a0x += al0 * r0.x; a0y += al0 * r0.y; a0z += al0 * r0.z; a0w += al0 * r0.w;
        a1x += al1 * r1.x; a1y += al1 * r1.y; a1z += al1 * r1.z; a1w += al1 * r1.w;
    }

    int c0 = lane * 4;
    float4 bb0 = *(const float4*)&b1[c0];
    float4 bb1 = *(const float4*)&b1[128 + c0];
    float v[8] = {a0x + bb0.x, a0y + bb0.y, a0z + bb0.z, a0w + bb0.w,
                  a1x + bb1.x, a1y + bb1.y, a1z + bb1.z, a1w + bb1.w};
    __nv_bfloat16 hh[8], ll[8];
#pragma unroll
    for (int i = 0; i < 8; i++) {
        float e = v[i] > 0.f ? v[i] : expm1f(v[i]);
        split2(e, hh[i], ll[i]);
    }
    size_t o0 = (size_t)node * H1C + c0;
    size_t o1 = o0 + 128;
    *(__nv_bfloat162*)&h2h[o0]     = __nv_bfloat162(hh[0], hh[1]);
    *(__nv_bfloat162*)&h2h[o0 + 2] = __nv_bfloat162(hh[2], hh[3]);
    *(__nv_bfloat162*)&h2h[o1]     = __nv_bfloat162(hh[4], hh[5]);
    *(__nv_bfloat162*)&h2h[o1 + 2] = __nv_bfloat162(hh[6], hh[7]);
    *(__nv_bfloat162*)&h2l[o0]     = __nv_bfloat162(ll[0], ll[1]);
    *(__nv_bfloat162*)&h2l[o0 + 2] = __nv_bfloat162(ll[2], ll[3]);
    *(__nv_bfloat162*)&h2l[o1]     = __nv_bfloat162(ll[4], ll[5]);
    *(__nv_bfloat162*)&h2l[o1 + 2] = __nv_bfloat162(ll[6], ll[7]);
}

// ============================================================================
// Layer-2 fused softmax + aggregate (+bias). One warp/node.
// ============================================================================
__global__ __launch_bounds__(256) void agg2_k(
    const float* __restrict__ G, const float* __restrict__ A2s, const float* __restrict__ A2d,
    const int* __restrict__ ptr, const int* __restrict__ csrsrc,
    const float* __restrict__ bmu, const float* __restrict__ bls,
    float* __restrict__ out)
{
    int node = (blockIdx.x * 256 + threadIdx.x) >> 5;
    if (node >= N_NODES) return;
    int lane = threadIdx.x & 31;
    int p0 = ptr[node], deg = ptr[node + 1] - p0;
    float2 ad = *(const float2*)&A2d[node * 2];

    float m0 = -1e30f, m1 = -1e30f;
    for (int base = 0; base < deg; base += 32) {
        int e = base + lane;
        if (e < deg) {
            int s = csrsrc[p0 + e];
            float2 as = *(const float2*)&A2s[s * 2];
            m0 = fmaxf(m0, lrelu(as.x + ad.x));
            m1 = fmaxf(m1, lrelu(as.y + ad.y));
        }
    }
#pragma unroll
    for (int o = 16; o; o >>= 1) {
        m0 = fmaxf(m0, __shfl_xor_sync(0xffffffffu, m0, o));
        m1 = fmaxf(m1, __shfl_xor_sync(0xffffffffu, m1, o));
    }
    float d0 = 0.f, d1 = 0.f;
    for (int base = 0; base < deg; base += 32) {
        int e = base + lane;
        if (e < deg) {
            int s = csrsrc[p0 + e];
            float2 as = *(const float2*)&A2s[s * 2];
            d0 += __expf(lrelu(as.x + ad.x) - m0);
            d1 += __expf(lrelu(as.y + ad.y) - m1);
        }
    }
#pragma unroll
    for (int o = 16; o; o >>= 1) {
        d0 += __shfl_xor_sync(0xffffffffu, d0, o);
        d1 += __shfl_xor_sync(0xffffffffu, d1, o);
    }
    float inv0 = 1.f / (d0 + 1e-16f), inv1 = 1.f / (d1 + 1e-16f);

    int h = lane >> 4;
    float ax = 0.f, ay = 0.f, az = 0.f, aw = 0.f;
#pragma unroll 2
    for (int e = 0; e < deg; e++) {
        int s = csrsrc[p0 + e];
        float2 as = *(const float2*)&A2s[s * 2];
        float al0 = __expf(lrelu(as.x + ad.x) - m0) * inv0;
        float al1 = __expf(lrelu(as.y + ad.y) - m1) * inv1;
        float al = h ? al1 : al0;
        float4 r = ((const float4*)(G + (size_t)s * 128))[lane];
        ax += al * r.x; ay += al * r.y; az += al * r.z; aw += al * r.w;
    }
    int cl = (lane & 15) * 4;
    float4 bb = h ? *(const float4*)&bls[cl] : *(const float4*)&bmu[cl];
    float* dp = out + (size_t)h * N_NODES * OUTC + (size_t)node * OUTC + cl;
    *(float4*)dp = make_float4(ax + bb.x, ay + bb.y, az + bb.z, aw + bb.w);
}

// ---------------- launch ----------------
extern "C" void kernel_launch(void* const* d_in, const int* in_sizes, int n_in,
                              void* d_out, int out_size) {
    const float* x        = (const float*)d_in[0];
    const int*   ei       = (const int*)  d_in[1];
    const float* W1       = (const float*)d_in[2];
    const float* att_src1 = (const float*)d_in[3];
    const float* att_dst1 = (const float*)d_in[4];
    const float* b1       = (const float*)d_in[5];
    const float* W_mu     = (const float*)d_in[6];
    const float* as_mu    = (const float*)d_in[7];
    const float* ad_mu    = (const float*)d_in[8];
    const float* b_mu     = (const float*)d_in[9];
    const float* W_ls     = (const float*)d_in[10];
    const float* as_ls    = (const float*)d_in[11];
    const float* ad_ls    = (const float*)d_in[12];
    const float* b_ls     = (const float*)d_in[13];
    float* out = (float*)d_out;

    float *H1, *Gcat, *A1s, *A1d, *A2s, *A2d, *a2s, *a2d;
    __nv_bfloat16 *H2hi, *H2lo, *W1Th, *W1Tl, *WcTh, *WcTl;
    int *deg, *ptr, *cursor, *csrsrc, *blockSum, *blockOff;
    cudaGetSymbolAddress((void**)&H1,   g_H1);
    cudaGetSymbolAddress((void**)&Gcat, g_Gcat);
    cudaGetSymbolAddress((void**)&A1s,  g_A1src);
    cudaGetSymbolAddress((void**)&A1d,  g_A1dst);
    cudaGetSymbolAddress((void**)&A2s,  g_A2src);
    cudaGetSymbolAddress((void**)&A2d,  g_A2dst);
    cudaGetSymbolAddress((void**)&a2s,  g_att2src);
    cudaGetSymbolAddress((void**)&a2d,  g_att2dst);
    cudaGetSymbolAddress((void**)&H2hi, g_H2hi);
    cudaGetSymbolAddress((void**)&H2lo, g_H2lo);
    cudaGetSymbolAddress((void**)&W1Th, g_W1T_hi);
    cudaGetSymbolAddress((void**)&W1Tl, g_W1T_lo);
    cudaGetSymbolAddress((void**)&WcTh, g_WcT_hi);
    cudaGetSymbolAddress((void**)&WcTl, g_WcT_lo);
    cudaGetSymbolAddress((void**)&deg,    g_deg);
    cudaGetSymbolAddress((void**)&ptr,    g_ptr);
    cudaGetSymbolAddress((void**)&cursor, g_cursor);
    cudaGetSymbolAddress((void**)&csrsrc, g_csrsrc);
    cudaGetSymbolAddress((void**)&blockSum, g_blockSum);
    cudaGetSymbolAddress((void**)&blockOff, g_blockOff);

    // ---- CSR build ----
    cudaMemsetAsync(deg, 0, N_NODES * sizeof(int));
    csr_count_k<<<(E_TOT + 255) / 256, 256>>>(ei, deg);
    scanA_k<<<NBLK, 256>>>(deg, ptr, blockSum);
    scanB_k<<<1, 256>>>(blockSum, blockOff);
    scanC_k<<<NBLK, 256>>>(ptr, blockOff, cursor);
    csr_fill_k<<<(E_TOT + 255) / 256, 256>>>(ei, cursor, csrsrc);

    // ---- data prep ----
    prep_k<<<(2 * 256 * 128 + 256 + 255) / 256, 256>>>(W1, W_mu, W_ls, as_mu, as_ls, ad_mu, ad_ls,
                                                       W1Th, W1Tl, WcTh, WcTl, a2s, a2d);

    const int gx = (N_NODES + 127) / 128;
    const int aggBlocks = (N_NODES * 32 + 255) / 256;

    // ---- layer 1 (A = x fp32, split in-kernel) ----
    gemm_mma<128, 256, 128, true><<<dim3(gx, 2), 256>>>(
        x, nullptr, nullptr, W1Th, W1Tl, H1, att_src1, att_dst1, A1s, A1d, N_NODES);
    agg1_k<<<aggBlocks, 256>>>(H1, A1s, A1d, ptr, csrsrc, b1, H2hi, H2lo);

    // ---- layer 2 ----
    gemm_mma<256, 128, 64, false><<<dim3(gx, 1), 256>>>(
        nullptr, H2hi, H2lo, WcTh, WcTl, Gcat, a2s, a2d, A2s, A2d, N_NODES);
    agg2_k<<<aggBlocks, 256>>>(Gcat, A2s, A2d, ptr, csrsrc, b_mu, b_ls, out);
}

// round 8
// speedup vs baseline: 2.6481x; 1.0671x over previous
#include <cuda_runtime.h>
#include <cuda_bf16.h>
#include <math.h>
#include <stdint.h>

#define N_NODES 50000
#define IN_CH   128
#define E_EDGES 400000
#define E_TOT   (E_EDGES + N_NODES)   // with self loops
#define HID     128                   // per-head channels of conv1
#define H1C     256                   // HEADS*HID
#define OUTC    64
#define NBLK    ((N_NODES + 255) / 256)   // scan blocks

// ---------------- scratch (device globals: allocation-free) ----------------
__device__ float g_H1  [(size_t)N_NODES * H1C];   // x @ W1 (fp32)
__device__ float g_Gcat[(size_t)N_NODES * 128];   // [h2 @ W_mu | h2 @ W_ls]
__device__ __nv_bfloat16 g_H2hi[(size_t)N_NODES * H1C];
__device__ __nv_bfloat16 g_H2lo[(size_t)N_NODES * H1C];
__device__ __nv_bfloat16 g_W1T_hi[256 * 128];   // [N=256 rows][K=128]
__device__ __nv_bfloat16 g_W1T_lo[256 * 128];
__device__ __nv_bfloat16 g_WcT_hi[128 * 256];   // [N=128 rows][K=256]
__device__ __nv_bfloat16 g_WcT_lo[128 * 256];
__device__ float g_A1src[N_NODES * 2];
__device__ float g_A1dst[N_NODES * 2];
__device__ float g_A2src[N_NODES * 2];
__device__ float g_A2dst[N_NODES * 2];
__device__ float g_att2src[128];   // [as_mu(64) | as_ls(64)]
__device__ float g_att2dst[128];   // [ad_mu(64) | ad_ls(64)]
__device__ float2 g_alpha[E_TOT];  // fallback scratch for deg>32 nodes
// CSR
__device__ int g_deg[N_NODES];
__device__ int g_ptr[N_NODES + 1];
__device__ int g_cursor[N_NODES];
__device__ int g_csrsrc[E_TOT];
__device__ int g_blockSum[NBLK];
__device__ int g_blockOff[NBLK];

// ---------------- low-level helpers ----------------
__device__ __forceinline__ uint32_t smem_u32(const void* p) {
    uint32_t a;
    asm("{ .reg .u64 t; cvta.to.shared.u64 t, %1; cvt.u32.u64 %0, t; }" : "=r"(a) : "l"(p));
    return a;
}
__device__ __forceinline__ void ldsm4(uint32_t* r, uint32_t addr) {
    asm volatile("ldmatrix.sync.aligned.m8n8.x4.shared.b16 {%0,%1,%2,%3}, [%4];"
                 : "=r"(r[0]), "=r"(r[1]), "=r"(r[2]), "=r"(r[3]) : "r"(addr));
}
__device__ __forceinline__ void mma_bf16(float* c, const uint32_t* a, uint32_t b0, uint32_t b1) {
    asm volatile("mma.sync.aligned.m16n8k16.row.col.f32.bf16.bf16.f32 "
                 "{%0,%1,%2,%3}, {%4,%5,%6,%7}, {%8,%9}, {%0,%1,%2,%3};"
                 : "+f"(c[0]), "+f"(c[1]), "+f"(c[2]), "+f"(c[3])
                 : "r"(a[0]), "r"(a[1]), "r"(a[2]), "r"(a[3]), "r"(b0), "r"(b1));
}
__device__ __forceinline__ float lrelu(float v) { return v > 0.f ? v : 0.2f * v; }
__device__ __forceinline__ void split2(float v, __nv_bfloat16& h, __nv_bfloat16& l) {
    h = __float2bfloat16(v);
    l = __float2bfloat16(v - __bfloat162float(h));
}
__device__ __forceinline__ float wmax(float v) {
#pragma unroll
    for (int o = 16; o; o >>= 1) v = fmaxf(v, __shfl_xor_sync(0xffffffffu, v, o));
    return v;
}
__device__ __forceinline__ float wsum(float v) {
#pragma unroll
    for (int o = 16; o; o >>= 1) v += __shfl_xor_sync(0xffffffffu, v, o);
    return v;
}

// ============================================================================
// Tensor-core GEMM (mma.sync bf16, hi/lo 3-product split) + fused attn logits.
// ============================================================================
template<int K, int NTOT, int CHEAD, bool AFP32>
__global__ __launch_bounds__(256, 2) void gemm_mma(
    const float* __restrict__ Afp,
    const __nv_bfloat16* __restrict__ Ahi, const __nv_bfloat16* __restrict__ Alo,
    const __nv_bfloat16* __restrict__ Bhi, const __nv_bfloat16* __restrict__ Blo,
    float* __restrict__ C,
    const float* __restrict__ attsrc, const float* __restrict__ attdst,
    float* __restrict__ asrc, float* __restrict__ adst, int M)
{
    __shared__ __align__(16) __nv_bfloat16 sAh[128 * 32];
    __shared__ __align__(16) __nv_bfloat16 sAl[128 * 32];
    __shared__ __align__(16) __nv_bfloat16 sBh[128 * 32];
    __shared__ __align__(16) __nv_bfloat16 sBl[128 * 32];
    __shared__ float sAtt[2][128];
    __shared__ float sRed[2][128][2];

    const int tid = threadIdx.x;
    const int lane = tid & 31;
    const int wid = tid >> 5;
    const int wr = wid & 3;
    const int wc = wid >> 2;
    const int m0 = blockIdx.x * 128;
    const int n0 = blockIdx.y * 128;

    for (int i = tid; i < 128; i += 256) {
        sAtt[0][i] = attsrc[n0 + i];
        sAtt[1][i] = attdst[n0 + i];
    }

    const uint32_t sAhB = smem_u32(sAh), sAlB = smem_u32(sAl);
    const uint32_t sBhB = smem_u32(sBh), sBlB = smem_u32(sBl);

    float acc[2][8][4];
#pragma unroll
    for (int i = 0; i < 2; i++)
#pragma unroll
        for (int j = 0; j < 8; j++)
#pragma unroll
            for (int l = 0; l < 4; l++) acc[i][j][l] = 0.f;

    const int a_row = wr * 32 + (lane & 7) + ((lane >> 3) & 1) * 8;
    const int a_chA = lane >> 4;
    const int b_row = wc * 64 + (lane & 7) + (lane >> 4) * 8;
    const int b_chB = (lane >> 3) & 1;

    for (int ks = 0; ks < K / 32; ks++) {
        if (AFP32) {
#pragma unroll
            for (int j = 0; j < 4; j++) {
                int idx = tid + j * 256;
                int row = idx >> 3, cg = idx & 7;
                int grA = m0 + row;
                float4 v = make_float4(0.f, 0.f, 0.f, 0.f);
                if (grA < M) v = *(const float4*)(Afp + (size_t)grA * K + ks * 32 + cg * 4);
                __nv_bfloat16 h0, h1, h2, h3, l0, l1, l2, l3;
                split2(v.x, h0, l0); split2(v.y, h1, l1);
                split2(v.z, h2, l2); split2(v.w, h3, l3);
                uint32_t soff = row * 64 + (((cg >> 1) ^ (row & 3)) << 4) + (cg & 1) * 8;
                __nv_bfloat162 hp0(h0, h1), hp1(h2, h3), lp0(l0, l1), lp1(l2, l3);
                *(uint2*)((char*)sAh + soff) = make_uint2(*(uint32_t*)&hp0, *(uint32_t*)&hp1);
                *(uint2*)((char*)sAl + soff) = make_uint2(*(uint32_t*)&lp0, *(uint32_t*)&lp1);
            }
        } else {
#pragma unroll
            for (int j = 0; j < 2; j++) {
                int idx = tid + j * 256;
                int row = idx >> 2, ch = idx & 3;
                uint32_t soff = row * 64 + ((ch ^ (row & 3)) << 4);
                int grA = m0 + row;
                size_t gofs = (size_t)grA * K + ks * 32 + ch * 8;
                uint4 va = make_uint4(0u, 0u, 0u, 0u), vb = va;
                if (grA < M) { va = *(const uint4*)(Ahi + gofs); vb = *(const uint4*)(Alo + gofs); }
                *(uint4*)((char*)sAh + soff) = va;
                *(uint4*)((char*)sAl + soff) = vb;
            }
        }
#pragma unroll
        for (int j = 0; j < 2; j++) {
            int idx = tid + j * 256;
            int row = idx >> 2, ch = idx & 3;
            uint32_t soff = row * 64 + ((ch ^ (row & 3)) << 4);
            size_t gofsB = (size_t)(n0 + row) * K + ks * 32 + ch * 8;
            *(uint4*)((char*)sBh + soff) = *(const uint4*)(Bhi + gofsB);
            *(uint4*)((char*)sBl + soff) = *(const uint4*)(Blo + gofsB);
        }
        __syncthreads();

#pragma unroll
        for (int k16 = 0; k16 < 2; k16++) {
            uint32_t ah[2][4], al[2][4];
#pragma unroll
            for (int mt = 0; mt < 2; mt++) {
                int row = a_row + mt * 16;
                int ch = k16 * 2 + a_chA;
                uint32_t off = row * 64 + ((ch ^ (row & 3)) << 4);
                ldsm4(ah[mt], sAhB + off);
                ldsm4(al[mt], sAlB + off);
            }
#pragma unroll
            for (int ntg = 0; ntg < 4; ntg++) {
                int row = b_row + ntg * 16;
                int ch = k16 * 2 + b_chB;
                uint32_t off = row * 64 + ((ch ^ (row & 3)) << 4);
                uint32_t bh[4], bl[4];
                ldsm4(bh, sBhB + off);
                ldsm4(bl, sBlB + off);
#pragma unroll
                for (int mt = 0; mt < 2; mt++) {
                    mma_bf16(acc[mt][ntg * 2 + 0], ah[mt], bh[0], bh[1]);
                    mma_bf16(acc[mt][ntg * 2 + 0], al[mt], bh[0], bh[1]);
                    mma_bf16(acc[mt][ntg * 2 + 0], ah[mt], bl[0], bl[1]);
                    mma_bf16(acc[mt][ntg * 2 + 1], ah[mt], bh[2], bh[3]);
                    mma_bf16(acc[mt][ntg * 2 + 1], al[mt], bh[2], bh[3]);
                    mma_bf16(acc[mt][ntg * 2 + 1], ah[mt], bl[2], bl[3]);
                }
            }
        }
        __syncthreads();
    }

    float pss[2][2] = {}, psd[2][2] = {};
#pragma unroll
    for (int mt = 0; mt < 2; mt++) {
        int rloc = wr * 32 + mt * 16 + (lane >> 2);
        int grow0 = m0 + rloc, grow1 = grow0 + 8;
#pragma unroll
        for (int nt = 0; nt < 8; nt++) {
            int cl = wc * 64 + nt * 8 + (lane & 3) * 2;
            float a0s = sAtt[0][cl], a1s = sAtt[0][cl + 1];
            float a0d = sAtt[1][cl], a1d = sAtt[1][cl + 1];
            float c0 = acc[mt][nt][0], c1 = acc[mt][nt][1];
            float c2 = acc[mt][nt][2], c3 = acc[mt][nt][3];
            pss[mt][0] += c0 * a0s + c1 * a1s;  psd[mt][0] += c0 * a0d + c1 * a1d;
            pss[mt][1] += c2 * a0s + c3 * a1s;  psd[mt][1] += c2 * a0d + c3 * a1d;
            if (grow0 < M) *(float2*)&C[(size_t)grow0 * NTOT + n0 + cl] = make_float2(c0, c1);
            if (grow1 < M) *(float2*)&C[(size_t)grow1 * NTOT + n0 + cl] = make_float2(c2, c3);
        }
    }
#pragma unroll
    for (int mt = 0; mt < 2; mt++)
#pragma unroll
        for (int h8 = 0; h8 < 2; h8++) {
            float vs = pss[mt][h8], vd = psd[mt][h8];
            vs += __shfl_xor_sync(0xffffffffu, vs, 1); vs += __shfl_xor_sync(0xffffffffu, vs, 2);
            vd += __shfl_xor_sync(0xffffffffu, vd, 1); vd += __shfl_xor_sync(0xffffffffu, vd, 2);
            if ((lane & 3) == 0) {
                int r = wr * 32 + mt * 16 + h8 * 8 + (lane >> 2);
                sRed[wc][r][0] = vs;
                sRed[wc][r][1] = vd;
            }
        }
    __syncthreads();
    for (int r = tid; r < 128; r += 256) {
        int node = m0 + r;
        if (node >= M) continue;
        if (CHEAD == 128) {
            int h = n0 >> 7;
            asrc[node * 2 + h] = sRed[0][r][0] + sRed[1][r][0];
            adst[node * 2 + h] = sRed[0][r][1] + sRed[1][r][1];
        } else {
            asrc[node * 2 + 0] = sRed[0][r][0];  adst[node * 2 + 0] = sRed[0][r][1];
            asrc[node * 2 + 1] = sRed[1][r][0];  adst[node * 2 + 1] = sRed[1][r][1];
        }
    }
}

// ---------------- prep ----------------
__global__ void prep_k(const float* __restrict__ W1,
                       const float* __restrict__ Wmu, const float* __restrict__ Wls,
                       const float* __restrict__ asmu, const float* __restrict__ asls,
                       const float* __restrict__ admu, const float* __restrict__ adls,
                       __nv_bfloat16* __restrict__ W1Th, __nv_bfloat16* __restrict__ W1Tl,
                       __nv_bfloat16* __restrict__ WcTh, __nv_bfloat16* __restrict__ WcTl,
                       float* __restrict__ a2s, float* __restrict__ a2d) {
    int i = blockIdx.x * blockDim.x + threadIdx.x;
    if (i < 256 * 128) {
        int n = i >> 7, k = i & 127;
        split2(W1[k * 256 + n], W1Th[i], W1Tl[i]);
    } else if (i < 2 * 256 * 128) {
        int j = i - 256 * 128;
        int n = j >> 8, k = j & 255;
        float w = (n < 64) ? Wmu[k * 64 + n] : Wls[k * 64 + (n - 64)];
        split2(w, WcTh[j], WcTl[j]);
    } else if (i < 2 * 256 * 128 + 128) {
        int j = i - 2 * 256 * 128;
        a2s[j] = (j < 64) ? asmu[j] : asls[j - 64];
    } else if (i < 2 * 256 * 128 + 256) {
        int j = i - 2 * 256 * 128 - 128;
        a2d[j] = (j < 64) ? admu[j] : adls[j - 64];
    }
}

// ---------------- CSR build ----------------
__global__ void csr_count_k(const int* __restrict__ ei, int* __restrict__ deg) {
    int e = blockIdx.x * blockDim.x + threadIdx.x;
    if (e >= E_TOT) return;
    int d = (e < E_EDGES) ? ei[E_EDGES + e] : e - E_EDGES;
    atomicAdd(&deg[d], 1);
}

__global__ void scanA_k(const int* __restrict__ deg, int* __restrict__ ptr,
                        int* __restrict__ blockSum) {
    __shared__ int sh[256];
    int i = blockIdx.x * 256 + threadIdx.x;
    int v = (i < N_NODES) ? deg[i] : 0;
    sh[threadIdx.x] = v;
    __syncthreads();
#pragma unroll
    for (int off = 1; off < 256; off <<= 1) {
        int t = (threadIdx.x >= off) ? sh[threadIdx.x - off] : 0;
        __syncthreads();
        sh[threadIdx.x] += t;
        __syncthreads();
    }
    if (i < N_NODES) ptr[i] = sh[threadIdx.x] - v;
    if (threadIdx.x == 255) blockSum[blockIdx.x] = sh[255];
}

__global__ void scanB_k(const int* __restrict__ blockSum, int* __restrict__ blockOff) {
    __shared__ int sh[256];
    int v = (threadIdx.x < NBLK) ? blockSum[threadIdx.x] : 0;
    sh[threadIdx.x] = v;
    __syncthreads();
#pragma unroll
    for (int off = 1; off < 256; off <<= 1) {
        int t = (threadIdx.x >= off) ? sh[threadIdx.x - off] : 0;
        __syncthreads();
        sh[threadIdx.x] += t;
        __syncthreads();
    }
    if (threadIdx.x < NBLK) blockOff[threadIdx.x] = sh[threadIdx.x] - v;
}

__global__ void scanC_k(int* __restrict__ ptr, const int* __restrict__ blockOff,
                        int* __restrict__ cursor) {
    int i = blockIdx.x * blockDim.x + threadIdx.x;
    if (i < N_NODES) {
        int v = ptr[i] + blockOff[i >> 8];
        ptr[i] = v;
        cursor[i] = v;
    }
    if (i == 0) ptr[N_NODES] = E_TOT;
}

__global__ void csr_fill_k(const int* __restrict__ ei, int* __restrict__ cursor,
                           int* __restrict__ csrsrc) {
    int e = blockIdx.x * blockDim.x + threadIdx.x;
    if (e >= E_TOT) return;
    int s, d;
    if (e < E_EDGES) { s = ei[e]; d = ei[E_EDGES + e]; }
    else             { s = d = e - E_EDGES; }
    int pos = atomicAdd(&cursor[d], 1);
    csrsrc[pos] = s;
}

// ============================================================================
// Warp softmax over incoming edges. Fast path (deg<=32): one parallel pass,
// alpha kept in registers. Fallback (deg>32): 3 passes via g_alpha scratch.
// Returns lane's (src, a0, a1) for fast path; fallback handled by caller loop.
// ============================================================================
__device__ __forceinline__ void warp_softmax(
    const float* __restrict__ As, float2 ad,
    const int* __restrict__ csrsrc, float2* __restrict__ alpha,
    int p0, int deg, int lane,
    int& sreg, float& a0, float& a1, float& inv0, float& inv1)
{
    if (deg <= 32) {
        sreg = 0;
        float l0 = -1e30f, l1 = -1e30f;
        if (lane < deg) {
            sreg = csrsrc[p0 + lane];
            float2 as = *(const float2*)&As[sreg * 2];
            l0 = lrelu(as.x + ad.x);
            l1 = lrelu(as.y + ad.y);
        }
        float m0 = wmax(l0), m1 = wmax(l1);
        float e0 = (lane < deg) ? __expf(l0 - m0) : 0.f;
        float e1 = (lane < deg) ? __expf(l1 - m1) : 0.f;
        inv0 = 1.f / (wsum(e0) + 1e-16f);
        inv1 = 1.f / (wsum(e1) + 1e-16f);
        a0 = e0 * inv0;
        a1 = e1 * inv1;
    } else {
        float m0 = -1e30f, m1 = -1e30f;
        for (int e = lane; e < deg; e += 32) {
            int s = csrsrc[p0 + e];
            float2 as = *(const float2*)&As[s * 2];
            m0 = fmaxf(m0, lrelu(as.x + ad.x));
            m1 = fmaxf(m1, lrelu(as.y + ad.y));
        }
        m0 = wmax(m0); m1 = wmax(m1);
        float d0 = 0.f, d1 = 0.f;
        for (int e = lane; e < deg; e += 32) {
            int s = csrsrc[p0 + e];
            float2 as = *(const float2*)&As[s * 2];
            float e0 = __expf(lrelu(as.x + ad.x) - m0);
            float e1 = __expf(lrelu(as.y + ad.y) - m1);
            alpha[p0 + e] = make_float2(e0, e1);
            d0 += e0; d1 += e1;
        }
        inv0 = 1.f / (wsum(d0) + 1e-16f);
        inv1 = 1.f / (wsum(d1) + 1e-16f);
        sreg = 0; a0 = 0.f; a1 = 0.f;   // caller reloads per chunk
    }
}

// ============================================================================
// Layer-1 fused softmax + aggregate (+bias, ELU, bf16 split). One warp/node.
// ============================================================================
__global__ __launch_bounds__(256) void agg1_k(
    const float* __restrict__ H1, const float* __restrict__ A1s, const float* __restrict__ A1d,
    const int* __restrict__ ptr, const int* __restrict__ csrsrc,
    float2* __restrict__ alpha, const float* __restrict__ b1,
    __nv_bfloat16* __restrict__ h2h, __nv_bfloat16* __restrict__ h2l)
{
    int node = (blockIdx.x * 256 + threadIdx.x) >> 5;
    if (node >= N_NODES) return;
    int lane = threadIdx.x & 31;
    int p0 = ptr[node], deg = ptr[node + 1] - p0;
    float2 ad = *(const float2*)&A1d[node * 2];

    int sreg; float a0, a1, inv0, inv1;
    warp_softmax(A1s, ad, csrsrc, alpha, p0, deg, lane, sreg, a0, a1, inv0, inv1);

    float c0[4] = {}, c1[4] = {};
    if (deg <= 32) {
#pragma unroll 4
        for (int j = 0; j < deg; j++) {
            int s = __shfl_sync(0xffffffffu, sreg, j);
            float al0 = __shfl_sync(0xffffffffu, a0, j);
            float al1 = __shfl_sync(0xffffffffu, a1, j);
            const float4* row = (const float4*)(H1 + (size_t)s * H1C);
            float4 r0 = row[lane], r1 = row[32 + lane];
            c0[0] += al0 * r0.x; c0[1] += al0 * r0.y; c0[2] += al0 * r0.z; c0[3] += al0 * r0.w;
            c1[0] += al1 * r1.x; c1[1] += al1 * r1.y; c1[2] += al1 * r1.z; c1[3] += al1 * r1.w;
        }
    } else {
        for (int base = 0; base < deg; base += 32) {
            int cnt = min(32, deg - base);
            int idx = p0 + base + lane;
            int sr = 0; float b0 = 0.f, b1v = 0.f;
            if (base + lane < deg) {
                sr = csrsrc[idx];
                float2 av = alpha[idx];
                b0 = av.x * inv0; b1v = av.y * inv1;
            }
            for (int j = 0; j < cnt; j++) {
                int s = __shfl_sync(0xffffffffu, sr, j);
                float al0 = __shfl_sync(0xffffffffu, b0, j);
                float al1 = __shfl_sync(0xffffffffu, b1v, j);
                const float4* row = (const float4*)(H1 + (size_t)s * H1C);
                float4 r0 = row[lane], r1 = row[32 + lane];
                c0[0] += al0 * r0.x; c0[1] += al0 * r0.y; c0[2] += al0 * r0.z; c0[3] += al0 * r0.w;
                c1[0] += al1 * r1.x; c1[1] += al1 * r1.y; c1[2] += al1 * r1.z; c1[3] += al1 * r1.w;
            }
        }
    }

    int ch0 = lane * 4;
    float4 bb0 = *(const float4*)&b1[ch0];
    float4 bb1 = *(const float4*)&b1[128 + ch0];
    float v[8] = {c0[0] + bb0.x, c0[1] + bb0.y, c0[2] + bb0.z, c0[3] + bb0.w,
                  c1[0] + bb1.x, c1[1] + bb1.y, c1[2] + bb1.z, c1[3] + bb1.w};
    __nv_bfloat16 hh[8], ll[8];
#pragma unroll
    for (int i = 0; i < 8; i++) {
        float e = v[i] > 0.f ? v[i] : expm1f(v[i]);
        split2(e, hh[i], ll[i]);
    }
    size_t o0 = (size_t)node * H1C + ch0;
    size_t o1 = o0 + 128;
    *(__nv_bfloat162*)&h2h[o0]     = __nv_bfloat162(hh[0], hh[1]);
    *(__nv_bfloat162*)&h2h[o0 + 2] = __nv_bfloat162(hh[2], hh[3]);
    *(__nv_bfloat162*)&h2h[o1]     = __nv_bfloat162(hh[4], hh[5]);
    *(__nv_bfloat162*)&h2h[o1 + 2] = __nv_bfloat162(hh[6], hh[7]);
    *(__nv_bfloat162*)&h2l[o0]     = __nv_bfloat162(ll[0], ll[1]);
    *(__nv_bfloat162*)&h2l[o0 + 2] = __nv_bfloat162(ll[2], ll[3]);
    *(__nv_bfloat162*)&h2l[o1]     = __nv_bfloat162(ll[4], ll[5]);
    *(__nv_bfloat162*)&h2l[o1 + 2] = __nv_bfloat162(ll[6], ll[7]);
}

// ============================================================================
// Layer-2 fused softmax + aggregate (+bias). One warp/node.
// ============================================================================
__global__ __launch_bounds__(256) void agg2_k(
    const float* __restrict__ G, const float* __restrict__ A2s, const float* __restrict__ A2d,
    const int* __restrict__ ptr, const int* __restrict__ csrsrc,
    float2* __restrict__ alpha,
    const float* __restrict__ bmu, const float* __restrict__ bls,
    float* __restrict__ out)
{
    int node = (blockIdx.x * 256 + threadIdx.x) >> 5;
    if (node >= N_NODES) return;
    int lane = threadIdx.x & 31;
    int p0 = ptr[node], deg = ptr[node + 1] - p0;
    float2 ad = *(const float2*)&A2d[node * 2];

    int sreg; float a0, a1, inv0, inv1;
    warp_softmax(A2s, ad, csrsrc, alpha, p0, deg, lane, sreg, a0, a1, inv0, inv1);

    int h = lane >> 4;   // lane's 4 channels belong to head h
    float cx = 0.f, cy = 0.f, cz = 0.f, cw = 0.f;
    if (deg <= 32) {
#pragma unroll 4
        for (int j = 0; j < deg; j++) {
            int s = __shfl_sync(0xffffffffu, sreg, j);
            float al0 = __shfl_sync(0xffffffffu, a0, j);
            float al1 = __shfl_sync(0xffffffffu, a1, j);
            float al = h ? al1 : al0;
            float4 r = ((const float4*)(G + (size_t)s * 128))[lane];
            cx += al * r.x; cy += al * r.y; cz += al * r.z; cw += al * r.w;
        }
    } else {
        for (int base = 0; base < deg; base += 32) {
            int cnt = min(32, deg - base);
            int idx = p0 + base + lane;
            int sr = 0; float b0 = 0.f, b1v = 0.f;
            if (base + lane < deg) {
                sr = csrsrc[idx];
                float2 av = alpha[idx];
                b0 = av.x * inv0; b1v = av.y * inv1;
            }
            for (int j = 0; j < cnt; j++) {
                int s = __shfl_sync(0xffffffffu, sr, j);
                float al0 = __shfl_sync(0xffffffffu, b0, j);
                float al1 = __shfl_sync(0xffffffffu, b1v, j);
                float al = h ? al1 : al0;
                float4 r = ((const float4*)(G + (size_t)s * 128))[lane];
                cx += al * r.x; cy += al * r.y; cz += al * r.z; cw += al * r.w;
            }
        }
    }
    int cl = (lane & 15) * 4;
    float4 bb = h ? *(const float4*)&bls[cl] : *(const float4*)&bmu[cl];
    float* dp = out + (size_t)h * N_NODES * OUTC + (size_t)node * OUTC + cl;
    *(float4*)dp = make_float4(cx + bb.x, cy + bb.y, cz + bb.z, cw + bb.w);
}

// ---------------- launch ----------------
extern "C" void kernel_launch(void* const* d_in, const int* in_sizes, int n_in,
                              void* d_out, int out_size) {
    const float* x        = (const float*)d_in[0];
    const int*   ei       = (const int*)  d_in[1];
    const float* W1       = (const float*)d_in[2];
    const float* att_src1 = (const float*)d_in[3];
    const float* att_dst1 = (const float*)d_in[4];
    const float* b1       = (const float*)d_in[5];
    const float* W_mu     = (const float*)d_in[6];
    const float* as_mu    = (const float*)d_in[7];
    const float* ad_mu    = (const float*)d_in[8];
    const float* b_mu     = (const float*)d_in[9];
    const float* W_ls     = (const float*)d_in[10];
    const float* as_ls    = (const float*)d_in[11];
    const float* ad_ls    = (const float*)d_in[12];
    const float* b_ls     = (const float*)d_in[13];
    float* out = (float*)d_out;

    float *H1, *Gcat, *A1s, *A1d, *A2s, *A2d, *a2s, *a2d;
    float2* alpha;
    __nv_bfloat16 *H2hi, *H2lo, *W1Th, *W1Tl, *WcTh, *WcTl;
    int *deg, *ptr, *cursor, *csrsrc, *blockSum, *blockOff;
    cudaGetSymbolAddress((void**)&H1,   g_H1);
    cudaGetSymbolAddress((void**)&Gcat, g_Gcat);
    cudaGetSymbolAddress((void**)&A1s,  g_A1src);
    cudaGetSymbolAddress((void**)&A1d,  g_A1dst);
    cudaGetSymbolAddress((void**)&A2s,  g_A2src);
    cudaGetSymbolAddress((void**)&A2d,  g_A2dst);
    cudaGetSymbolAddress((void**)&a2s,  g_att2src);
    cudaGetSymbolAddress((void**)&a2d,  g_att2dst);
    cudaGetSymbolAddress((void**)&alpha, g_alpha);
    cudaGetSymbolAddress((void**)&H2hi, g_H2hi);
    cudaGetSymbolAddress((void**)&H2lo, g_H2lo);
    cudaGetSymbolAddress((void**)&W1Th, g_W1T_hi);
    cudaGetSymbolAddress((void**)&W1Tl, g_W1T_lo);
    cudaGetSymbolAddress((void**)&WcTh, g_WcT_hi);
    cudaGetSymbolAddress((void**)&WcTl, g_WcT_lo);
    cudaGetSymbolAddress((void**)&deg,    g_deg);
    cudaGetSymbolAddress((void**)&ptr,    g_ptr);
    cudaGetSymbolAddress((void**)&cursor, g_cursor);
    cudaGetSymbolAddress((void**)&csrsrc, g_csrsrc);
    cudaGetSymbolAddress((void**)&blockSum, g_blockSum);
    cudaGetSymbolAddress((void**)&blockOff, g_blockOff);

    // ---- CSR build ----
    cudaMemsetAsync(deg, 0, N_NODES * sizeof(int));
    csr_count_k<<<(E_TOT + 255) / 256, 256>>>(ei, deg);
    scanA_k<<<NBLK, 256>>>(deg, ptr, blockSum);
    scanB_k<<<1, 256>>>(blockSum, blockOff);
    scanC_k<<<NBLK, 256>>>(ptr, blockOff, cursor);
    csr_fill_k<<<(E_TOT + 255) / 256, 256>>>(ei, cursor, csrsrc);

    // ---- data prep ----
    prep_k<<<(2 * 256 * 128 + 256 + 255) / 256, 256>>>(W1, W_mu, W_ls, as_mu, as_ls, ad_mu, ad_ls,
                                                       W1Th, W1Tl, WcTh, WcTl, a2s, a2d);

    const int gx = (N_NODES + 127) / 128;
    const int aggBlocks = (N_NODES * 32 + 255) / 256;

    // ---- layer 1 ----
    gemm_mma<128, 256, 128, true><<<dim3(gx, 2), 256>>>(
        x, nullptr, nullptr, W1Th, W1Tl, H1, att_src1, att_dst1, A1s, A1d, N_NODES);
    agg1_k<<<aggBlocks, 256>>>(H1, A1s, A1d, ptr, csrsrc, alpha, b1, H2hi, H2lo);

    // ---- layer 2 ----
    gemm_mma<256, 128, 64, false><<<dim3(gx, 1), 256>>>(
        nullptr, H2hi, H2lo, WcTh, WcTl, Gcat, a2s, a2d, A2s, A2d, N_NODES);
    agg2_k<<<aggBlocks, 256>>>(Gcat, A2s, A2d, ptr, csrsrc, alpha, b_mu, b_ls, out);
}